// round 1
// baseline (speedup 1.0000x reference)
#include <cuda_runtime.h>
#include <math.h>

#define NB  2
#define CH  288
#define HP  4096   // query pixels (64x64)
#define KPP 1024   // key pixels (32x32)
#define NH  9
#define DH  32
#define TQ  16

// ---------------- device scratch (static, no runtime allocation) ----------------
__device__ float g_Q  [NB*HP*CH];      // q[n][p][o], o = m*32+dd
__device__ float g_KT [NB*KPP*CH];     // k[n][kp][o] (key-major)
__device__ float g_V  [NB*KPP*CH];     // v[n][kp][o]
__device__ float g_O  [NB*HP*CH];      // attention output pre-proj: O[n][p][o]
__device__ float g_PFX[NH*64*32*DH];   // pfx[m][w][wk][dd]
__device__ float g_PFY[NH*64*32*DH];   // pfy[m][h][hk][dd]
__device__ float g_mixw[NB*NH];

// =================================================================================
// Kernel 1: Q/K/V projections.  out[n][row][o] = sum_c x[n][c][pix(row)] * W[o][c]
// BM=64 rows x BN=64 o, BK=32, 256 threads, 4x4 register tile per thread.
// grid.z: 0,1 = Q (n=0,1); 2,3 = K; 4,5 = V
// =================================================================================
__global__ __launch_bounds__(256) void qkv_kernel(
    const float* __restrict__ x,
    const float* __restrict__ Wq,
    const float* __restrict__ Wk,
    const float* __restrict__ Wv)
{
    int which = blockIdx.z >> 1;
    int n     = blockIdx.z & 1;
    int rows  = (which == 0) ? HP : KPP;
    int p0    = blockIdx.x * 64;
    if (p0 >= rows) return;
    int o0    = blockIdx.y * 64;

    const float* W = (which == 0) ? Wq : (which == 1 ? Wk : Wv);
    float* out = (which == 0) ? (g_Q + (size_t)n*HP*CH)
                              : ((which == 1 ? g_KT : g_V) + (size_t)n*KPP*CH);
    const float* xb = x + (size_t)n*CH*HP;

    __shared__ float As[32][64];
    __shared__ float Bs[32][68];

    int t  = threadIdx.x;
    int tx = t & 15, ty = t >> 4;
    float acc[4][4] = {};

    for (int c0 = 0; c0 < CH; c0 += 32) {
#pragma unroll
        for (int i = 0; i < 8; i++) {
            int idx = t + i*256;
            int c = idx >> 6, pix = idx & 63;
            int row = p0 + pix;
            int pixel = (which == 0) ? row : (((row >> 5) << 7) | ((row & 31) << 1));
            As[c][pix] = xb[(size_t)(c0 + c)*HP + pixel];
        }
#pragma unroll
        for (int i = 0; i < 8; i++) {
            int idx = t + i*256;
            int o = idx >> 5, c = idx & 31;
            int oo = o0 + o;
            Bs[c][o] = (oo < CH) ? W[(size_t)oo*CH + c0 + c] : 0.f;
        }
        __syncthreads();
#pragma unroll
        for (int c = 0; c < 32; c++) {
            float4 a = *(const float4*)&As[c][ty*4];
            float4 b = *(const float4*)&Bs[c][tx*4];
            acc[0][0] += a.x*b.x; acc[0][1] += a.x*b.y; acc[0][2] += a.x*b.z; acc[0][3] += a.x*b.w;
            acc[1][0] += a.y*b.x; acc[1][1] += a.y*b.y; acc[1][2] += a.y*b.z; acc[1][3] += a.y*b.w;
            acc[2][0] += a.z*b.x; acc[2][1] += a.z*b.y; acc[2][2] += a.z*b.z; acc[2][3] += a.z*b.w;
            acc[3][0] += a.w*b.x; acc[3][1] += a.w*b.y; acc[3][2] += a.w*b.z; acc[3][3] += a.w*b.w;
        }
        __syncthreads();
    }
    int o = o0 + tx*4;
    if (o < CH) {
#pragma unroll
        for (int i = 0; i < 4; i++) {
            int row = p0 + ty*4 + i;
            float4 v = make_float4(acc[i][0], acc[i][1], acc[i][2], acc[i][3]);
            *(float4*)&out[(size_t)row*CH + o] = v;
        }
    }
}

// =================================================================================
// Kernel 2: positional factor tables.
//   pf[m][a][b][dd] = (1/sqrt2) * sum_f emb[f] * W[m*32+dd][f]
//   emb[f<72] = sin(diff/dm[f]); emb[72+f] = cos(diff/dm[f]); diff = a - 2b.
// grid.x = 2048 (a*32+b), grid.y = 0 -> PFX(Wx), 1 -> PFY(Wy). block = 144 threads.
// =================================================================================
__global__ void pf_kernel(const float* __restrict__ Wx, const float* __restrict__ Wy)
{
    int a = blockIdx.x >> 5;
    int b = blockIdx.x & 31;
    const float* W = blockIdx.y ? Wy : Wx;
    float* out = blockIdx.y ? g_PFY : g_PFX;

    __shared__ float emb[144];
    int t = threadIdx.x;
    float diff = (float)a - 2.0f*(float)b;
    if (t < 72) {
        float dm  = powf(1000.0f, (4.0f/288.0f)*(float)t);
        float arg = diff / dm;
        emb[t]      = sinf(arg);
        emb[72 + t] = cosf(arg);
    }
    __syncthreads();
    const float inv_sqrt2 = 0.7071067811865476f;
    for (int j = t; j < CH; j += 144) {
        float s = 0.f;
        const float* wr = W + (size_t)j*144;
#pragma unroll 8
        for (int f = 0; f < 144; f++) s += emb[f]*wr[f];
        int m = j >> 5, dd = j & 31;
        out[(((size_t)m*64 + a)*32 + b)*32 + dd] = s * inv_sqrt2;
    }
}

// =================================================================================
// Kernel 3: context mean + head-mix softmax.  2 blocks (per n), 288 threads.
// =================================================================================
__global__ void ctx_kernel(const float* __restrict__ Wc, const float* __restrict__ bc)
{
    int n = blockIdx.x;
    int t = threadIdx.x;
    __shared__ float cs[CH];
    __shared__ float lg[NH];

    const float* q = g_Q + (size_t)n*HP*CH;
    float s = 0.f;
    for (int p = 0; p < HP; p++) s += q[(size_t)p*CH + t];
    cs[t] = s * (1.0f/HP);
    __syncthreads();
    if (t < NH) {
        float l = bc[t];
        const float* wr = Wc + (size_t)t*CH;
        for (int o = 0; o < CH; o++) l += cs[o]*wr[o];
        lg[t] = l;
    }
    __syncthreads();
    if (t == 0) {
        float mx = lg[0];
        for (int j = 1; j < NH; j++) mx = fmaxf(mx, lg[j]);
        float e[NH], sum = 0.f;
        for (int j = 0; j < NH; j++) { e[j] = expf(lg[j]-mx); sum += e[j]; }
        for (int j = 0; j < NH; j++) g_mixw[n*NH + j] = e[j]/sum;
    }
}

// =================================================================================
// Kernel 4: fused attention. One block per (n, tile of 16 queries). 256 threads.
// smem: Qs[16][288] | Eb[16][1024] | Ab[16][1024] | Ks[32][260] | exs[512] | eys[512]
// For each head m: E = Q_m K_m^T + pos-bias -> row softmax -> Ab += mixw_m * P.
// Then O = Ab @ V (V staged through the freed Eb region, 32 keys/chunk).
// =================================================================================
#define SM_E   4608
#define SM_A   (4608 + 16384)
#define SM_KS  (4608 + 16384 + 16384)
#define SM_EX  (SM_KS + 32*260)
#define SM_EY  (SM_EX + 512)
#define SM_TOT (SM_EY + 512)   // 46720 floats = 186,880 bytes

__global__ __launch_bounds__(256, 1) void attn_kernel()
{
    extern __shared__ float sm[];
    float* Qs  = sm;
    float* Eb  = sm + SM_E;
    float* Ab  = sm + SM_A;
    float* Ks  = sm + SM_KS;
    float* exs = sm + SM_EX;
    float* eys = sm + SM_EY;

    int n  = blockIdx.y;
    int q0 = blockIdx.x * TQ;
    int h  = q0 >> 6;
    int wbase = q0 & 63;
    int t  = threadIdx.x;
    int warp = t >> 5, lane = t & 31;

    // ---- load Q tile (16 x 288) ----
    {
        const float4* src = (const float4*)(g_Q + ((size_t)n*HP + q0)*CH);
        float4* dst = (float4*)Qs;
#pragma unroll
        for (int i = 0; i < 5; i++) {
            int idx = t + i*256;
            if (idx < 1152) dst[idx] = src[idx];
        }
    }
    __syncthreads();

    int k4 = (t & 63) * 4;      // this thread's 4 keys (within a 256-key chunk)
    int qb = (t >> 6) * 4;      // this thread's 4 queries

    for (int m = 0; m < NH; m++) {
        float mw = g_mixw[n*NH + m];

        // ---- positional bias: exs[qi][wk], eys[qi][hk] (warp-cooperative dots) ----
        for (int i = 0; i < 64; i++) {
            int e  = warp*64 + i;
            int qi = e >> 5, kk = e & 31;
            float qv = Qs[qi*CH + m*DH + lane];
            float px = g_PFX[((((size_t)m*64) + wbase + qi)*32 + kk)*32 + lane];
            float py = g_PFY[((((size_t)m*64) + h)*32 + kk)*32 + lane];
            float vx = qv*px, vy = qv*py;
#pragma unroll
            for (int s2 = 16; s2; s2 >>= 1) {
                vx += __shfl_xor_sync(0xffffffffu, vx, s2);
                vy += __shfl_xor_sync(0xffffffffu, vy, s2);
            }
            if (lane == 0) { exs[e] = vx; eys[e] = vy; }
        }
        __syncthreads();

        // ---- energy: E[16][1024] in 4 chunks of 256 keys ----
        for (int ch = 0; ch < 4; ch++) {
            {   // stage K chunk transposed: Ks[dd][key]
                const float* src = g_KT + ((size_t)(n*KPP + ch*256 + t))*CH + m*DH;
#pragma unroll
                for (int u = 0; u < 8; u++) {
                    float4 kf = *(const float4*)(src + u*4);
                    Ks[(4*u+0)*260 + t] = kf.x;
                    Ks[(4*u+1)*260 + t] = kf.y;
                    Ks[(4*u+2)*260 + t] = kf.z;
                    Ks[(4*u+3)*260 + t] = kf.w;
                }
            }
            __syncthreads();

            float acc[4][4] = {};
#pragma unroll
            for (int d4 = 0; d4 < 8; d4++) {
                float qs[4][4];
#pragma unroll
                for (int u = 0; u < 4; u++) {
                    float4 qq = *(const float4*)&Qs[(qb+u)*CH + m*DH + d4*4];
                    qs[u][0] = qq.x; qs[u][1] = qq.y; qs[u][2] = qq.z; qs[u][3] = qq.w;
                }
#pragma unroll
                for (int v = 0; v < 4; v++) {
                    float4 kv = *(const float4*)&Ks[(d4*4+v)*260 + k4];
#pragma unroll
                    for (int u = 0; u < 4; u++) {
                        float qv = qs[u][v];
                        acc[u][0] += qv*kv.x;
                        acc[u][1] += qv*kv.y;
                        acc[u][2] += qv*kv.z;
                        acc[u][3] += qv*kv.w;
                    }
                }
            }
#pragma unroll
            for (int u = 0; u < 4; u++) {
                int qi = qb + u;
#pragma unroll
                for (int v = 0; v < 4; v++) {
                    int kp = ch*256 + k4 + v;
                    Eb[qi*KPP + kp] = acc[u][v] + exs[qi*32 + (kp & 31)] + eys[qi*32 + (kp >> 5)];
                }
            }
            __syncthreads();
        }

        // ---- row softmax + weighted accumulate into Ab (2 rows per warp) ----
#pragma unroll
        for (int rr = 0; rr < 2; rr++) {
            int qi = warp*2 + rr;
            float* row = Eb + qi*KPP;
            float mx = -1e30f;
#pragma unroll 8
            for (int j = 0; j < 32; j++) mx = fmaxf(mx, row[lane + j*32]);
#pragma unroll
            for (int s2 = 16; s2; s2 >>= 1) mx = fmaxf(mx, __shfl_xor_sync(0xffffffffu, mx, s2));
            float sum = 0.f;
#pragma unroll 8
            for (int j = 0; j < 32; j++) {
                float p = __expf(row[lane + j*32] - mx);
                row[lane + j*32] = p;
                sum += p;
            }
#pragma unroll
            for (int s2 = 16; s2; s2 >>= 1) sum += __shfl_xor_sync(0xffffffffu, sum, s2);
            float sc = mw / sum;
            float* arow = Ab + qi*KPP;
            if (m == 0) {
#pragma unroll 8
                for (int j = 0; j < 32; j++) arow[lane + j*32] = row[lane + j*32]*sc;
            } else {
#pragma unroll 8
                for (int j = 0; j < 32; j++) arow[lane + j*32] += row[lane + j*32]*sc;
            }
        }
        __syncthreads();
    }

    // ---- PV: O[16][288] = Ab[16][1024] @ V[1024][288], V staged via Eb ----
    int qi_r[5], oq_r[5];
#pragma unroll
    for (int r = 0; r < 5; r++) {
        int task = r*256 + t;           // 1152 tasks = 16 q x 72 o-quads
        qi_r[r] = task / 72;
        oq_r[r] = task % 72;
    }
    bool v4ok = (t < 128);              // task range for r=4 is 1024..1151
    float4 oac[5];
#pragma unroll
    for (int r = 0; r < 5; r++) oac[r] = make_float4(0.f,0.f,0.f,0.f);

    float* Vs = Eb;                     // 32 keys x 288 = 9216 floats <= 16384
    for (int chv = 0; chv < 32; chv++) {
        {
            const float4* src = (const float4*)(g_V + ((size_t)(n*KPP + chv*32))*CH);
            float4* dst = (float4*)Vs;
#pragma unroll
            for (int i = 0; i < 9; i++) dst[t + i*256] = src[t + i*256];
        }
        __syncthreads();
#pragma unroll
        for (int r = 0; r < 5; r++) {
            if (r == 4 && !v4ok) break;
            const float* arow = Ab + qi_r[r]*KPP + chv*32;
            const float* vb   = Vs + oq_r[r]*4;
            float4 a = oac[r];
#pragma unroll
            for (int kl = 0; kl < 32; kl += 2) {
                float2 a2 = *(const float2*)(arow + kl);
                float4 v0 = *(const float4*)(vb + kl*CH);
                float4 v1 = *(const float4*)(vb + (kl+1)*CH);
                a.x += a2.x*v0.x + a2.y*v1.x;
                a.y += a2.x*v0.y + a2.y*v1.y;
                a.z += a2.x*v0.z + a2.y*v1.z;
                a.w += a2.x*v0.w + a2.y*v1.w;
            }
            oac[r] = a;
        }
        __syncthreads();
    }
#pragma unroll
    for (int r = 0; r < 5; r++) {
        if (r == 4 && !v4ok) break;
        *(float4*)(g_O + ((size_t)(n*HP + q0 + qi_r[r]))*CH + oq_r[r]*4) = oac[r];
    }
}

// =================================================================================
// Kernel 5: final projection + residual.
//   out[n][o][p] = gamma*( sum_c Wp[o][c]*O[n][p][c] + bproj[o] ) + x[n][o][p]
// =================================================================================
__global__ __launch_bounds__(256) void proj_kernel(
    const float* __restrict__ x,
    const float* __restrict__ Wp,
    const float* __restrict__ bp,
    const float* __restrict__ gamma,
    float* __restrict__ out)
{
    int n  = blockIdx.z;
    int p0 = blockIdx.x * 64;
    int o0 = blockIdx.y * 64;
    const float* A = g_O + (size_t)n*HP*CH;

    __shared__ float As[32][68];
    __shared__ float Bs[32][68];

    int t  = threadIdx.x;
    int tx = t & 15, ty = t >> 4;
    float acc[4][4] = {};   // [oj][ri]

    for (int c0 = 0; c0 < CH; c0 += 32) {
#pragma unroll
        for (int i = 0; i < 8; i++) {
            int idx = t + i*256;
            int pix = idx >> 5, c = idx & 31;
            As[c][pix] = A[(size_t)(p0 + pix)*CH + c0 + c];
        }
#pragma unroll
        for (int i = 0; i < 8; i++) {
            int idx = t + i*256;
            int o = idx >> 5, c = idx & 31;
            int oo = o0 + o;
            Bs[c][o] = (oo < CH) ? Wp[(size_t)oo*CH + c0 + c] : 0.f;
        }
        __syncthreads();
#pragma unroll
        for (int c = 0; c < 32; c++) {
            float4 a = *(const float4*)&As[c][tx*4];   // 4 pixels
            float4 b = *(const float4*)&Bs[c][ty*4];   // 4 output channels
            acc[0][0] += b.x*a.x; acc[0][1] += b.x*a.y; acc[0][2] += b.x*a.z; acc[0][3] += b.x*a.w;
            acc[1][0] += b.y*a.x; acc[1][1] += b.y*a.y; acc[1][2] += b.y*a.z; acc[1][3] += b.y*a.w;
            acc[2][0] += b.z*a.x; acc[2][1] += b.z*a.y; acc[2][2] += b.z*a.z; acc[2][3] += b.z*a.w;
            acc[3][0] += b.w*a.x; acc[3][1] += b.w*a.y; acc[3][2] += b.w*a.z; acc[3][3] += b.w*a.w;
        }
        __syncthreads();
    }
    float g = gamma[0];
#pragma unroll
    for (int j = 0; j < 4; j++) {
        int o = o0 + ty*4 + j;
        if (o < CH) {
            float bb = bp[o];
            size_t base = (size_t)n*CH*HP + (size_t)o*HP + p0 + tx*4;
            float4 xr = *(const float4*)(x + base);
            float4 v;
            v.x = g*(acc[j][0] + bb) + xr.x;
            v.y = g*(acc[j][1] + bb) + xr.y;
            v.z = g*(acc[j][2] + bb) + xr.z;
            v.w = g*(acc[j][3] + bb) + xr.w;
            *(float4*)(out + base) = v;
        }
    }
}

// =================================================================================
extern "C" void kernel_launch(void* const* d_in, const int* in_sizes, int n_in,
                              void* d_out, int out_size)
{
    const float* x     = (const float*)d_in[0];
    const float* Wq    = (const float*)d_in[1];
    const float* Wk    = (const float*)d_in[2];
    const float* Wv    = (const float*)d_in[3];
    const float* Wx    = (const float*)d_in[4];
    const float* Wy    = (const float*)d_in[5];
    const float* Wproj = (const float*)d_in[6];
    const float* bproj = (const float*)d_in[7];
    const float* Wc    = (const float*)d_in[8];
    const float* bc    = (const float*)d_in[9];
    const float* gamma = (const float*)d_in[10];
    float* out = (float*)d_out;

    cudaFuncSetAttribute(attn_kernel, cudaFuncAttributeMaxDynamicSharedMemorySize,
                         SM_TOT * (int)sizeof(float));

    qkv_kernel<<<dim3(64, 5, 6), 256>>>(x, Wq, Wk, Wv);
    pf_kernel<<<dim3(2048, 2), 144>>>(Wx, Wy);
    ctx_kernel<<<2, 288>>>(Wc, bc);
    attn_kernel<<<dim3(HP/TQ, NB), 256, SM_TOT * (int)sizeof(float)>>>();
    proj_kernel<<<dim3(64, 5, 2), 256>>>(x, Wproj, bproj, gamma, out);
}

// round 2
// speedup vs baseline: 1.0492x; 1.0492x over previous
#include <cuda_runtime.h>
#include <math.h>

#define NB  2
#define CH  288
#define HP  4096   // query pixels (64x64)
#define KPP 1024   // key pixels (32x32)
#define NH  9
#define DH  32
#define TQ  16

// ---------------- device scratch (static, no runtime allocation) ----------------
__device__ float g_Q  [NB*HP*CH];       // q[n][p][o], o = m*32+dd
__device__ float g_KTd[NB*NH*DH*KPP];   // k[n][m][dd][kp]  (key-contiguous, per head)
__device__ float g_V  [NB*KPP*CH];      // v[n][kp][o]
__device__ float g_O  [NB*HP*CH];       // attention output pre-proj: O[n][p][o]
__device__ float g_PFX[NH*64*32*DH];    // pfx[m][w][wk][dd]
__device__ float g_PFY[NH*64*32*DH];    // pfy[m][h][hk][dd]
__device__ float g_mixw[NB*NH];

// =================================================================================
// Kernel 1: Q/K/V projections.  out[n][row][o] = sum_c x[n][c][pix(row)] * W[o][c]
// BM=64 rows x BN=64 o, BK=32, 256 threads, 4x4 register tile per thread.
// grid.z: 0,1 = Q (n=0,1); 2,3 = K; 4,5 = V.  K is scattered to g_KTd layout.
// =================================================================================
__global__ __launch_bounds__(256) void qkv_kernel(
    const float* __restrict__ x,
    const float* __restrict__ Wq,
    const float* __restrict__ Wk,
    const float* __restrict__ Wv)
{
    int which = blockIdx.z >> 1;
    int n     = blockIdx.z & 1;
    int rows  = (which == 0) ? HP : KPP;
    int p0    = blockIdx.x * 64;
    if (p0 >= rows) return;
    int o0    = blockIdx.y * 64;

    const float* W = (which == 0) ? Wq : (which == 1 ? Wk : Wv);
    const float* xb = x + (size_t)n*CH*HP;

    __shared__ float As[32][64];
    __shared__ float Bs[32][68];

    int t  = threadIdx.x;
    int tx = t & 15, ty = t >> 4;
    float acc[4][4] = {};

    for (int c0 = 0; c0 < CH; c0 += 32) {
#pragma unroll
        for (int i = 0; i < 8; i++) {
            int idx = t + i*256;
            int c = idx >> 6, pix = idx & 63;
            int row = p0 + pix;
            int pixel = (which == 0) ? row : (((row >> 5) << 7) | ((row & 31) << 1));
            As[c][pix] = xb[(size_t)(c0 + c)*HP + pixel];
        }
#pragma unroll
        for (int i = 0; i < 8; i++) {
            int idx = t + i*256;
            int o = idx >> 5, c = idx & 31;
            int oo = o0 + o;
            Bs[c][o] = (oo < CH) ? W[(size_t)oo*CH + c0 + c] : 0.f;
        }
        __syncthreads();
#pragma unroll
        for (int c = 0; c < 32; c++) {
            float4 a = *(const float4*)&As[c][ty*4];
            float4 b = *(const float4*)&Bs[c][tx*4];
            acc[0][0] += a.x*b.x; acc[0][1] += a.x*b.y; acc[0][2] += a.x*b.z; acc[0][3] += a.x*b.w;
            acc[1][0] += a.y*b.x; acc[1][1] += a.y*b.y; acc[1][2] += a.y*b.z; acc[1][3] += a.y*b.w;
            acc[2][0] += a.z*b.x; acc[2][1] += a.z*b.y; acc[2][2] += a.z*b.z; acc[2][3] += a.z*b.w;
            acc[3][0] += a.w*b.x; acc[3][1] += a.w*b.y; acc[3][2] += a.w*b.z; acc[3][3] += a.w*b.w;
        }
        __syncthreads();
    }
    int o = o0 + tx*4;
    if (o >= CH) return;

    if (which == 1) {
        // scatter K into per-head transposed layout: g_KTd[n][m][dd][row]
#pragma unroll
        for (int i = 0; i < 4; i++) {
            int row = p0 + ty*4 + i;
#pragma unroll
            for (int c = 0; c < 4; c++) {
                int oo = o + c;
                g_KTd[(((size_t)n*NH + (oo >> 5))*DH + (oo & 31))*KPP + row] = acc[i][c];
            }
        }
    } else {
        float* out = (which == 0) ? (g_Q + (size_t)n*HP*CH) : (g_V + (size_t)n*KPP*CH);
#pragma unroll
        for (int i = 0; i < 4; i++) {
            int row = p0 + ty*4 + i;
            float4 v = make_float4(acc[i][0], acc[i][1], acc[i][2], acc[i][3]);
            *(float4*)&out[(size_t)row*CH + o] = v;
        }
    }
}

// =================================================================================
// Kernel 2: positional factor tables.
// =================================================================================
__global__ void pf_kernel(const float* __restrict__ Wx, const float* __restrict__ Wy)
{
    int a = blockIdx.x >> 5;
    int b = blockIdx.x & 31;
    const float* W = blockIdx.y ? Wy : Wx;
    float* out = blockIdx.y ? g_PFY : g_PFX;

    __shared__ float emb[144];
    int t = threadIdx.x;
    float diff = (float)a - 2.0f*(float)b;
    if (t < 72) {
        float dm  = powf(1000.0f, (4.0f/288.0f)*(float)t);
        float arg = diff / dm;
        emb[t]      = sinf(arg);
        emb[72 + t] = cosf(arg);
    }
    __syncthreads();
    const float inv_sqrt2 = 0.7071067811865476f;
    for (int j = t; j < CH; j += 144) {
        float s = 0.f;
        const float* wr = W + (size_t)j*144;
#pragma unroll 8
        for (int f = 0; f < 144; f++) s += emb[f]*wr[f];
        int m = j >> 5, dd = j & 31;
        out[(((size_t)m*64 + a)*32 + b)*32 + dd] = s * inv_sqrt2;
    }
}

// =================================================================================
// Kernel 3: context mean + head-mix softmax.  2 blocks (per n), 576 threads.
// =================================================================================
__global__ __launch_bounds__(576) void ctx_kernel(const float* __restrict__ Wc, const float* __restrict__ bc)
{
    int n = blockIdx.x;
    int t = threadIdx.x;
    __shared__ float part[576];
    __shared__ float cs[CH];
    __shared__ float lg[NH];

    int c = (t < CH) ? t : t - CH;
    int slice = (t < CH) ? 0 : 1;
    const float* q = g_Q + (size_t)n*HP*CH + (size_t)slice*(HP/2)*CH + c;
    float s = 0.f;
#pragma unroll 8
    for (int p = 0; p < HP/2; p++) s += q[(size_t)p*CH];
    part[t] = s;
    __syncthreads();
    if (t < CH) cs[t] = (part[t] + part[t+CH]) * (1.0f/HP);
    __syncthreads();
    if (t < NH) {
        float l = bc[t];
        const float* wr = Wc + (size_t)t*CH;
#pragma unroll 8
        for (int o = 0; o < CH; o++) l += cs[o]*wr[o];
        lg[t] = l;
    }
    __syncthreads();
    if (t == 0) {
        float mx = lg[0];
        for (int j = 1; j < NH; j++) mx = fmaxf(mx, lg[j]);
        float e[NH], sum = 0.f;
        for (int j = 0; j < NH; j++) { e[j] = expf(lg[j]-mx); sum += e[j]; }
        for (int j = 0; j < NH; j++) g_mixw[n*NH + j] = e[j]/sum;
    }
}

// =================================================================================
// Kernel 4: fused attention. One block per (n, tile of 16 queries). 512 threads.
// smem: Qs[16][288] | Eb[16][1024] | Ab[16][1024] | Ks[32][516] | exs[512] | eys[512]
// =================================================================================
#define KSP  516
#define SM_E   (16*CH)                       // 4608
#define SM_A   (SM_E + 16*KPP)               // +16384
#define SM_KS  (SM_A + 16*KPP)               // +16384
#define SM_EX  (SM_KS + 32*KSP)              // +16512
#define SM_EY  (SM_EX + 512)
#define SM_TOT (SM_EY + 512)                 // 54912 floats = 219,648 B

__global__ __launch_bounds__(512, 1) void attn_kernel()
{
    extern __shared__ float sm[];
    float* Qs  = sm;
    float* Eb  = sm + SM_E;
    float* Ab  = sm + SM_A;
    float* Ks  = sm + SM_KS;
    float* exs = sm + SM_EX;
    float* eys = sm + SM_EY;

    int n  = blockIdx.y;
    int q0 = blockIdx.x * TQ;
    int h  = q0 >> 6;
    int wbase = q0 & 63;
    int t  = threadIdx.x;
    int warp = t >> 5, lane = t & 31;

    // ---- load Q tile (16 x 288) ----
    {
        const float4* src = (const float4*)(g_Q + ((size_t)n*HP + q0)*CH);
        float4* dst = (float4*)Qs;
#pragma unroll
        for (int i = 0; i < 3; i++) {
            int idx = t + i*512;
            if (idx < 1152) dst[idx] = src[idx];
        }
    }
    __syncthreads();

    const int kq = (t & 127) * 4;     // this thread's 4 keys in a 512-key chunk
    const int qb = (t >> 7) * 4;      // this thread's 4 queries

    for (int m = 0; m < NH; m++) {
        float mw = g_mixw[n*NH + m];

        // ---- positional bias: one ex and one ey dot per thread (no shuffles) ----
        {
            int qi = warp, kk = lane;                 // 16 warps x 32 lanes = 512
            const float* qp = Qs + qi*CH + m*DH;
            const float* px = g_PFX + (((size_t)m*64 + wbase + qi)*32 + kk)*32;
            const float* py = g_PFY + (((size_t)m*64 + h)*32 + kk)*32;
            float sx = 0.f, sy = 0.f;
#pragma unroll
            for (int d = 0; d < DH; d++) {
                float qv = qp[d];
                sx += qv * px[d];
                sy += qv * py[d];
            }
            exs[t] = sx; eys[t] = sy;
        }

        // ---- energy: E[16][1024] in 2 chunks of 512 keys ----
        for (int ch = 0; ch < 2; ch++) {
            __syncthreads();   // Ks reuse safe + exs visible
            {   // stage K chunk: Ks[dd][key], straight coalesced copy
                const float* kb = g_KTd + (((size_t)n*NH + m)*DH)*KPP + ch*512;
#pragma unroll
                for (int i = 0; i < 8; i++) {
                    int e  = t + i*512;
                    int dd = e >> 7, j4 = (e & 127)*4;
                    *(float4*)&Ks[dd*KSP + j4] = *(const float4*)&kb[(size_t)dd*KPP + j4];
                }
            }
            __syncthreads();

            float acc[4][4] = {};
#pragma unroll
            for (int d4 = 0; d4 < 8; d4++) {
                float qs[4][4];
#pragma unroll
                for (int u = 0; u < 4; u++) {
                    float4 qq = *(const float4*)&Qs[(qb+u)*CH + m*DH + d4*4];
                    qs[u][0] = qq.x; qs[u][1] = qq.y; qs[u][2] = qq.z; qs[u][3] = qq.w;
                }
#pragma unroll
                for (int v = 0; v < 4; v++) {
                    float4 kv = *(const float4*)&Ks[(d4*4+v)*KSP + kq];
#pragma unroll
                    for (int u = 0; u < 4; u++) {
                        float qv = qs[u][v];
                        acc[u][0] += qv*kv.x;
                        acc[u][1] += qv*kv.y;
                        acc[u][2] += qv*kv.z;
                        acc[u][3] += qv*kv.w;
                    }
                }
            }
            int kb0 = ch*512 + kq;
            int wk  = kb0 & 31;
            int hk  = kb0 >> 5;
#pragma unroll
            for (int u = 0; u < 4; u++) {
                int qi = qb + u;
                float ey = eys[qi*32 + hk];
                float4 e;
                e.x = acc[u][0] + exs[qi*32 + wk    ] + ey;
                e.y = acc[u][1] + exs[qi*32 + wk + 1] + ey;
                e.z = acc[u][2] + exs[qi*32 + wk + 2] + ey;
                e.w = acc[u][3] + exs[qi*32 + wk + 3] + ey;
                *(float4*)&Eb[qi*KPP + kb0] = e;
            }
        }
        __syncthreads();

        // ---- row softmax + weighted accumulate into Ab (1 row per warp) ----
        {
            int qi = warp;
            float* row = Eb + qi*KPP;
            float mx = -1e30f;
#pragma unroll 8
            for (int j = 0; j < 32; j++) mx = fmaxf(mx, row[lane + j*32]);
#pragma unroll
            for (int s2 = 16; s2; s2 >>= 1) mx = fmaxf(mx, __shfl_xor_sync(0xffffffffu, mx, s2));
            float sum = 0.f;
#pragma unroll 8
            for (int j = 0; j < 32; j++) {
                float p = __expf(row[lane + j*32] - mx);
                row[lane + j*32] = p;
                sum += p;
            }
#pragma unroll
            for (int s2 = 16; s2; s2 >>= 1) sum += __shfl_xor_sync(0xffffffffu, sum, s2);
            float sc = mw / sum;
            float* arow = Ab + qi*KPP;
            if (m == 0) {
#pragma unroll 8
                for (int j = 0; j < 32; j++) arow[lane + j*32] = row[lane + j*32]*sc;
            } else {
#pragma unroll 8
                for (int j = 0; j < 32; j++) arow[lane + j*32] += row[lane + j*32]*sc;
            }
        }
        // no trailing sync needed: next-iter writes (exs, Ks) are guarded by the
        // sync at the top of the chunk loop; softmax touches only Eb/Ab.
    }
    __syncthreads();

    // ---- PV: O[16][288] = Ab[16][1024] @ V[1024][288] ----
    // tasks: 8 query-pairs x 72 col-quads = 576; thread t handles t and (512+t<576)
    int qp0 = t / 72,  oq0 = t % 72;          // task r=0 (always valid)
    int t1  = 512 + t;
    int qp1 = t1 / 72, oq1 = t1 % 72;         // task r=1 (valid for t<64)
    bool has1 = (t < 64);

    float4 o00 = make_float4(0,0,0,0), o01 = make_float4(0,0,0,0);
    float4 o10 = make_float4(0,0,0,0), o11 = make_float4(0,0,0,0);

    float* Vs = Eb;   // 32 keys x 288 = 9216 floats
    for (int chv = 0; chv < 32; chv++) {
        {
            const float4* src = (const float4*)(g_V + ((size_t)(n*KPP + chv*32))*CH);
            float4* dst = (float4*)Vs;
#pragma unroll
            for (int i = 0; i < 5; i++) {
                int idx = t + i*512;
                if (idx < 2304) dst[idx] = src[idx];
            }
        }
        __syncthreads();

        {   // task 0: rows qp0*2, qp0*2+1, cols oq0*4..+3
            const float* a0 = Ab + (qp0*2    )*KPP + chv*32;
            const float* a1 = Ab + (qp0*2 + 1)*KPP + chv*32;
            const float* vb = Vs + oq0*4;
#pragma unroll 4
            for (int kl = 0; kl < 32; kl++) {
                float4 vv = *(const float4*)(vb + kl*CH);
                float w0 = a0[kl], w1 = a1[kl];
                o00.x += w0*vv.x; o00.y += w0*vv.y; o00.z += w0*vv.z; o00.w += w0*vv.w;
                o01.x += w1*vv.x; o01.y += w1*vv.y; o01.z += w1*vv.z; o01.w += w1*vv.w;
            }
        }
        if (has1) {
            const float* a0 = Ab + (qp1*2    )*KPP + chv*32;
            const float* a1 = Ab + (qp1*2 + 1)*KPP + chv*32;
            const float* vb = Vs + oq1*4;
#pragma unroll 4
            for (int kl = 0; kl < 32; kl++) {
                float4 vv = *(const float4*)(vb + kl*CH);
                float w0 = a0[kl], w1 = a1[kl];
                o10.x += w0*vv.x; o10.y += w0*vv.y; o10.z += w0*vv.z; o10.w += w0*vv.w;
                o11.x += w1*vv.x; o11.y += w1*vv.y; o11.z += w1*vv.z; o11.w += w1*vv.w;
            }
        }
        __syncthreads();
    }
    {
        float* ob = g_O + ((size_t)(n*HP + q0))*CH;
        *(float4*)&ob[(size_t)(qp0*2    )*CH + oq0*4] = o00;
        *(float4*)&ob[(size_t)(qp0*2 + 1)*CH + oq0*4] = o01;
        if (has1) {
            *(float4*)&ob[(size_t)(qp1*2    )*CH + oq1*4] = o10;
            *(float4*)&ob[(size_t)(qp1*2 + 1)*CH + oq1*4] = o11;
        }
    }
}

// =================================================================================
// Kernel 5: final projection + residual.
// =================================================================================
__global__ __launch_bounds__(256) void proj_kernel(
    const float* __restrict__ x,
    const float* __restrict__ Wp,
    const float* __restrict__ bp,
    const float* __restrict__ gamma,
    float* __restrict__ out)
{
    int n  = blockIdx.z;
    int p0 = blockIdx.x * 64;
    int o0 = blockIdx.y * 64;
    const float* A = g_O + (size_t)n*HP*CH;

    __shared__ float As[32][68];
    __shared__ float Bs[32][68];

    int t  = threadIdx.x;
    int tx = t & 15, ty = t >> 4;
    float acc[4][4] = {};

    for (int c0 = 0; c0 < CH; c0 += 32) {
#pragma unroll
        for (int i = 0; i < 8; i++) {
            int idx = t + i*256;
            int pix = idx >> 5, c = idx & 31;
            As[c][pix] = A[(size_t)(p0 + pix)*CH + c0 + c];
        }
#pragma unroll
        for (int i = 0; i < 8; i++) {
            int idx = t + i*256;
            int o = idx >> 5, c = idx & 31;
            int oo = o0 + o;
            Bs[c][o] = (oo < CH) ? Wp[(size_t)oo*CH + c0 + c] : 0.f;
        }
        __syncthreads();
#pragma unroll
        for (int c = 0; c < 32; c++) {
            float4 a = *(const float4*)&As[c][tx*4];
            float4 b = *(const float4*)&Bs[c][ty*4];
            acc[0][0] += b.x*a.x; acc[0][1] += b.x*a.y; acc[0][2] += b.x*a.z; acc[0][3] += b.x*a.w;
            acc[1][0] += b.y*a.x; acc[1][1] += b.y*a.y; acc[1][2] += b.y*a.z; acc[1][3] += b.y*a.w;
            acc[2][0] += b.z*a.x; acc[2][1] += b.z*a.y; acc[2][2] += b.z*a.z; acc[2][3] += b.z*a.w;
            acc[3][0] += b.w*a.x; acc[3][1] += b.w*a.y; acc[3][2] += b.w*a.z; acc[3][3] += b.w*a.w;
        }
        __syncthreads();
    }
    float g = gamma[0];
#pragma unroll
    for (int j = 0; j < 4; j++) {
        int o = o0 + ty*4 + j;
        if (o < CH) {
            float bb = bp[o];
            size_t base = (size_t)n*CH*HP + (size_t)o*HP + p0 + tx*4;
            float4 xr = *(const float4*)(x + base);
            float4 v;
            v.x = g*(acc[j][0] + bb) + xr.x;
            v.y = g*(acc[j][1] + bb) + xr.y;
            v.z = g*(acc[j][2] + bb) + xr.z;
            v.w = g*(acc[j][3] + bb) + xr.w;
            *(float4*)(out + base) = v;
        }
    }
}

// =================================================================================
extern "C" void kernel_launch(void* const* d_in, const int* in_sizes, int n_in,
                              void* d_out, int out_size)
{
    const float* x     = (const float*)d_in[0];
    const float* Wq    = (const float*)d_in[1];
    const float* Wk    = (const float*)d_in[2];
    const float* Wv    = (const float*)d_in[3];
    const float* Wx    = (const float*)d_in[4];
    const float* Wy    = (const float*)d_in[5];
    const float* Wproj = (const float*)d_in[6];
    const float* bproj = (const float*)d_in[7];
    const float* Wc    = (const float*)d_in[8];
    const float* bc    = (const float*)d_in[9];
    const float* gamma = (const float*)d_in[10];
    float* out = (float*)d_out;

    cudaFuncSetAttribute(attn_kernel, cudaFuncAttributeMaxDynamicSharedMemorySize,
                         SM_TOT * (int)sizeof(float));

    qkv_kernel<<<dim3(64, 5, 6), 256>>>(x, Wq, Wk, Wv);
    pf_kernel<<<dim3(2048, 2), 144>>>(Wx, Wy);
    ctx_kernel<<<2, 576>>>(Wc, bc);
    attn_kernel<<<dim3(HP/TQ, NB), 512, SM_TOT * (int)sizeof(float)>>>();
    proj_kernel<<<dim3(64, 5, 2), 256>>>(x, Wproj, bproj, gamma, out);
}

// round 5
// speedup vs baseline: 1.2409x; 1.1827x over previous
#include <cuda_runtime.h>
#include <math.h>

#define NB  2
#define CH  288
#define HP  4096
#define KPP 1024
#define NH  9
#define DH  32
#define TQ  16

typedef unsigned long long ull;

// ---- packed f32x2 FMA (sm_103a FFMA2; PTX-only path) ----
#define FMA2(d, a, b) asm("fma.rn.f32x2 %0, %1, %2, %0;" : "+l"(d) : "l"(a), "l"(b))
#define PK2(d, lo, hi) asm("mov.b64 %0, {%1, %2};" : "=l"(d) : "r"(__float_as_uint(lo)), "r"(__float_as_uint(hi)))
#define UPK2(lo, hi, v) do { unsigned int _ul, _uh; \
    asm("mov.b64 {%0, %1}, %2;" : "=r"(_ul), "=r"(_uh) : "l"(v)); \
    (lo) = __uint_as_float(_ul); (hi) = __uint_as_float(_uh); } while (0)

// ---------------- device scratch ----------------
__device__ float g_Q   [NB*HP*CH];
__device__ float g_KTd [NB*NH*DH*KPP];   // k[n][m][dd][kp]
__device__ float g_V   [NB*KPP*CH];
__device__ float g_O   [NB*HP*CH];
__device__ float g_PFX [NH*64*32*DH];
__device__ float g_PFY [NH*64*32*DH];
__device__ float g_Atn [NB*HP*KPP];      // combined attention weights
__device__ float g_ctxp[NB*32*CH];
__device__ float g_mixw[NB*NH];

// =================================================================================
// Kernel 1: Q/K/V projections (FFMA2 inner).
// =================================================================================
__global__ __launch_bounds__(256) void qkv_kernel(
    const float* __restrict__ x,
    const float* __restrict__ Wq,
    const float* __restrict__ Wk,
    const float* __restrict__ Wv)
{
    int which = blockIdx.z >> 1;
    int n     = blockIdx.z & 1;
    int rows  = (which == 0) ? HP : KPP;
    int p0    = blockIdx.x * 64;
    if (p0 >= rows) return;
    int o0    = blockIdx.y * 64;

    const float* W = (which == 0) ? Wq : (which == 1 ? Wk : Wv);
    const float* xb = x + (size_t)n*CH*HP;

    __shared__ float As[32][64];
    __shared__ float Bs[32][68];

    int t  = threadIdx.x;
    int tx = t & 15, ty = t >> 4;
    ull acc2[4][2] = {};

    for (int c0 = 0; c0 < CH; c0 += 32) {
#pragma unroll
        for (int i = 0; i < 8; i++) {
            int idx = t + i*256;
            int c = idx >> 6, pix = idx & 63;
            int row = p0 + pix;
            int pixel = (which == 0) ? row : (((row >> 5) << 7) | ((row & 31) << 1));
            As[c][pix] = xb[(size_t)(c0 + c)*HP + pixel];
        }
#pragma unroll
        for (int i = 0; i < 8; i++) {
            int idx = t + i*256;
            int o = idx >> 5, c = idx & 31;
            int oo = o0 + o;
            Bs[c][o] = (oo < CH) ? W[(size_t)oo*CH + c0 + c] : 0.f;
        }
        __syncthreads();
#pragma unroll
        for (int c = 0; c < 32; c++) {
            float4 a = *(const float4*)&As[c][ty*4];
            ulonglong2 b2 = *(const ulonglong2*)&Bs[c][tx*4];
            ull pa;
            PK2(pa, a.x, a.x); FMA2(acc2[0][0], pa, b2.x); FMA2(acc2[0][1], pa, b2.y);
            PK2(pa, a.y, a.y); FMA2(acc2[1][0], pa, b2.x); FMA2(acc2[1][1], pa, b2.y);
            PK2(pa, a.z, a.z); FMA2(acc2[2][0], pa, b2.x); FMA2(acc2[2][1], pa, b2.y);
            PK2(pa, a.w, a.w); FMA2(acc2[3][0], pa, b2.x); FMA2(acc2[3][1], pa, b2.y);
        }
        __syncthreads();
    }
    float acc[4][4];
#pragma unroll
    for (int i = 0; i < 4; i++) {
        UPK2(acc[i][0], acc[i][1], acc2[i][0]);
        UPK2(acc[i][2], acc[i][3], acc2[i][1]);
    }
    int o = o0 + tx*4;
    if (o >= CH) return;

    if (which == 1) {
#pragma unroll
        for (int i = 0; i < 4; i++) {
            int row = p0 + ty*4 + i;
#pragma unroll
            for (int c = 0; c < 4; c++) {
                int oo = o + c;
                g_KTd[(((size_t)n*NH + (oo >> 5))*DH + (oo & 31))*KPP + row] = acc[i][c];
            }
        }
    } else {
        float* out = (which == 0) ? (g_Q + (size_t)n*HP*CH) : (g_V + (size_t)n*KPP*CH);
#pragma unroll
        for (int i = 0; i < 4; i++) {
            int row = p0 + ty*4 + i;
            *(float4*)&out[(size_t)row*CH + o] =
                make_float4(acc[i][0], acc[i][1], acc[i][2], acc[i][3]);
        }
    }
}

// =================================================================================
// Kernel 2: positional factor tables.
// =================================================================================
__global__ void pf_kernel(const float* __restrict__ Wx, const float* __restrict__ Wy)
{
    int a = blockIdx.x >> 5;
    int b = blockIdx.x & 31;
    const float* W = blockIdx.y ? Wy : Wx;
    float* out = blockIdx.y ? g_PFY : g_PFX;

    __shared__ float emb[144];
    int t = threadIdx.x;
    float diff = (float)a - 2.0f*(float)b;
    if (t < 72) {
        float dm  = powf(1000.0f, (4.0f/288.0f)*(float)t);
        float arg = diff / dm;
        emb[t]      = sinf(arg);
        emb[72 + t] = cosf(arg);
    }
    __syncthreads();
    const float inv_sqrt2 = 0.7071067811865476f;
    for (int j = t; j < CH; j += 144) {
        float s = 0.f;
        const float* wr = W + (size_t)j*144;
#pragma unroll 8
        for (int f = 0; f < 144; f++) s += emb[f]*wr[f];
        int m = j >> 5, dd = j & 31;
        out[(((size_t)m*64 + a)*32 + b)*32 + dd] = s * inv_sqrt2;
    }
}

// =================================================================================
// Kernel 3a/3b: context mean (two-stage) + head-mix softmax.
// =================================================================================
__global__ __launch_bounds__(288) void ctx1_kernel()
{
    int n = blockIdx.y, b = blockIdx.x, t = threadIdx.x;
    const float* q = g_Q + ((size_t)n*HP + b*128)*CH + t;
    float s = 0.f;
#pragma unroll 8
    for (int p = 0; p < 128; p++) s += q[(size_t)p*CH];
    g_ctxp[((size_t)n*32 + b)*CH + t] = s;
}

__global__ __launch_bounds__(288) void ctx2_kernel(const float* __restrict__ Wc,
                                                   const float* __restrict__ bc)
{
    int n = blockIdx.x, t = threadIdx.x;
    __shared__ float cs[CH];
    __shared__ float lg[NH];
    float s = 0.f;
#pragma unroll
    for (int b = 0; b < 32; b++) s += g_ctxp[((size_t)n*32 + b)*CH + t];
    cs[t] = s * (1.0f/HP);
    __syncthreads();
    if (t < NH) {
        float l = bc[t];
        const float* wr = Wc + (size_t)t*CH;
#pragma unroll 8
        for (int o = 0; o < CH; o++) l += cs[o]*wr[o];
        lg[t] = l;
    }
    __syncthreads();
    if (t == 0) {
        float mx = lg[0];
        for (int j = 1; j < NH; j++) mx = fmaxf(mx, lg[j]);
        float e[NH], sum = 0.f;
        for (int j = 0; j < NH; j++) { e[j] = expf(lg[j]-mx); sum += e[j]; }
        for (int j = 0; j < NH; j++) g_mixw[n*NH + j] = e[j]/sum;
    }
}

// =================================================================================
// Kernel 4: attention energies + softmax + head mix -> g_Atn.  512 thr/block.
// Thread owns E for 4 queries x 8 keys, all in registers.
// =================================================================================
#define KSP   516
#define AE_QS 0
#define AE_KS (16*CH)
#define AE_EX (AE_KS + 32*KSP)
#define AE_EY (AE_EX + 512)
#define AE_RD (AE_EY + 512)
#define AE_TOT (AE_RD + 128)     // 22272 floats = 89,088 B

__global__ __launch_bounds__(512, 1) void attn_e_kernel()
{
    extern __shared__ float sm[];
    float* Qs  = sm + AE_QS;
    float* Ks  = sm + AE_KS;
    float* exs = sm + AE_EX;
    float* eys = sm + AE_EY;
    float* red = sm + AE_RD;

    int n  = blockIdx.y;
    int q0 = blockIdx.x * TQ;
    int h  = q0 >> 6;
    int wbase = q0 & 63;
    int t  = threadIdx.x;
    int warp = t >> 5, lane = t & 31;

    // load Q tile (16 x 288)
    {
        const float4* src = (const float4*)(g_Q + ((size_t)n*HP + q0)*CH);
        float4* dst = (float4*)Qs;
#pragma unroll
        for (int i = 0; i < 3; i++) {
            int idx = t + i*512;
            if (idx < 1152) dst[idx] = src[idx];
        }
    }

    const int kq   = (t & 127) * 4;
    const int qb   = (t >> 7) * 4;
    const int grp  = t >> 7;         // query group 0..3
    const int wgrp = warp & 3;       // warp within group

    float ab[4][8] = {};

    for (int m = 0; m < NH; m++) {
        float mw = g_mixw[n*NH + m];

        float e[4][8];
        for (int ch = 0; ch < 2; ch++) {
            __syncthreads();   // prior Ks/exs consumers done (and Q tile visible)
            if (ch == 0) {
                int qi = warp, kk = lane;
                const float* qp = Qs + qi*CH + m*DH;
                const float* px = g_PFX + (((size_t)m*64 + wbase + qi)*32 + kk)*32;
                const float* py = g_PFY + (((size_t)m*64 + h)*32 + kk)*32;
                float sx = 0.f, sy = 0.f;
#pragma unroll
                for (int d = 0; d < DH; d++) {
                    float qv = qp[d];
                    sx += qv * px[d];
                    sy += qv * py[d];
                }
                exs[t] = sx; eys[t] = sy;
            }
            {   // stage K chunk: Ks[dd][key]
                const float* kb = g_KTd + (((size_t)n*NH + m)*DH)*KPP + ch*512;
#pragma unroll
                for (int i = 0; i < 8; i++) {
                    int ee = t + i*512;
                    int dd = ee >> 7, j4 = (ee & 127)*4;
                    *(float4*)&Ks[dd*KSP + j4] = *(const float4*)&kb[(size_t)dd*KPP + j4];
                }
            }
            __syncthreads();

            ull acc2[4][2] = {};
#pragma unroll
            for (int d4 = 0; d4 < 8; d4++) {
                ulonglong2 kv0 = *(const ulonglong2*)&Ks[(d4*4+0)*KSP + kq];
                ulonglong2 kv1 = *(const ulonglong2*)&Ks[(d4*4+1)*KSP + kq];
                ulonglong2 kv2 = *(const ulonglong2*)&Ks[(d4*4+2)*KSP + kq];
                ulonglong2 kv3 = *(const ulonglong2*)&Ks[(d4*4+3)*KSP + kq];
#pragma unroll
                for (int u = 0; u < 4; u++) {
                    float4 qq = *(const float4*)&Qs[(qb+u)*CH + m*DH + d4*4];
                    ull pa;
                    PK2(pa, qq.x, qq.x); FMA2(acc2[u][0], pa, kv0.x); FMA2(acc2[u][1], pa, kv0.y);
                    PK2(pa, qq.y, qq.y); FMA2(acc2[u][0], pa, kv1.x); FMA2(acc2[u][1], pa, kv1.y);
                    PK2(pa, qq.z, qq.z); FMA2(acc2[u][0], pa, kv2.x); FMA2(acc2[u][1], pa, kv2.y);
                    PK2(pa, qq.w, qq.w); FMA2(acc2[u][0], pa, kv3.x); FMA2(acc2[u][1], pa, kv3.y);
                }
            }
            int kp0 = ch*512 + kq;
            int wk  = kp0 & 31;
            int hk  = kp0 >> 5;
#pragma unroll
            for (int u = 0; u < 4; u++) {
                int qi = qb + u;
                float ey = eys[qi*32 + hk];
                float a0,a1,a2,a3;
                UPK2(a0,a1,acc2[u][0]);
                UPK2(a2,a3,acc2[u][1]);
                e[u][ch*4+0] = a0 + exs[qi*32 + wk    ] + ey;
                e[u][ch*4+1] = a1 + exs[qi*32 + wk + 1] + ey;
                e[u][ch*4+2] = a2 + exs[qi*32 + wk + 2] + ey;
                e[u][ch*4+3] = a3 + exs[qi*32 + wk + 3] + ey;
            }
        }

        // ---- softmax across the row (128 threads per query group) ----
        float mx[4];
#pragma unroll
        for (int u = 0; u < 4; u++) {
            float v = e[u][0];
#pragma unroll
            for (int j = 1; j < 8; j++) v = fmaxf(v, e[u][j]);
#pragma unroll
            for (int s2 = 16; s2; s2 >>= 1) v = fmaxf(v, __shfl_xor_sync(0xffffffffu, v, s2));
            mx[u] = v;
        }
        if (lane == 0) {
#pragma unroll
            for (int u = 0; u < 4; u++) red[grp*16 + wgrp*4 + u] = mx[u];
        }
        __syncthreads();
#pragma unroll
        for (int u = 0; u < 4; u++) {
            float v = red[grp*16 + u];
            v = fmaxf(v, red[grp*16 + 4 + u]);
            v = fmaxf(v, red[grp*16 + 8 + u]);
            v = fmaxf(v, red[grp*16 + 12 + u]);
            mx[u] = v;
        }
        float sme[4];
#pragma unroll
        for (int u = 0; u < 4; u++) {
            float s = 0.f;
#pragma unroll
            for (int j = 0; j < 8; j++) {
                float p = __expf(e[u][j] - mx[u]);
                e[u][j] = p;
                s += p;
            }
#pragma unroll
            for (int s2 = 16; s2; s2 >>= 1) s += __shfl_xor_sync(0xffffffffu, s, s2);
            sme[u] = s;
        }
        if (lane == 0) {
#pragma unroll
            for (int u = 0; u < 4; u++) red[64 + grp*16 + wgrp*4 + u] = sme[u];
        }
        __syncthreads();
#pragma unroll
        for (int u = 0; u < 4; u++) {
            float s = red[64 + grp*16 + u] + red[64 + grp*16 + 4 + u]
                    + red[64 + grp*16 + 8 + u] + red[64 + grp*16 + 12 + u];
            float sc = mw / s;
#pragma unroll
            for (int j = 0; j < 8; j++) ab[u][j] += e[u][j] * sc;
        }
    }

    // write combined attention to g_Atn
#pragma unroll
    for (int u = 0; u < 4; u++) {
        float* arow = g_Atn + ((size_t)n*HP + q0 + qb + u)*KPP;
        *(float4*)&arow[kq]       = make_float4(ab[u][0], ab[u][1], ab[u][2], ab[u][3]);
        *(float4*)&arow[512 + kq] = make_float4(ab[u][4], ab[u][5], ab[u][6], ab[u][7]);
    }
}

// =================================================================================
// Kernel 5: PV GEMM.  O[n][row][o] = sum_kp Atn[n][row][kp] * V[n][kp][o]
// BM=128, BN=96, BK=16, 256 threads, 8x6 per thread, FFMA2.
// =================================================================================
__global__ __launch_bounds__(256) void pv_kernel()
{
    int n    = blockIdx.z;
    int row0 = blockIdx.x * 128;
    int o0   = blockIdx.y * 96;

    __shared__ float As[16][132];
    __shared__ float Bs[16][96];

    int t  = threadIdx.x;
    int tx = t & 15, ty = t >> 4;

    const float* A = g_Atn + ((size_t)n*HP + row0)*KPP;
    const float* V = g_V + (size_t)n*KPP*CH + o0;

    ull acc2[8][3] = {};

    for (int k0 = 0; k0 < KPP; k0 += 16) {
#pragma unroll
        for (int i = 0; i < 8; i++) {
            int e = t + i*256;
            int row = e >> 4, k = e & 15;
            As[k][row] = A[(size_t)row*KPP + k0 + k];
        }
#pragma unroll
        for (int i = 0; i < 6; i++) {
            int e = t + i*256;
            int k = e / 96, col = e % 96;
            Bs[k][col] = V[(size_t)(k0 + k)*CH + col];
        }
        __syncthreads();
#pragma unroll
        for (int k = 0; k < 16; k++) {
            float4 a0 = *(const float4*)&As[k][ty*8];
            float4 a1 = *(const float4*)&As[k][ty*8 + 4];
            ull b0 = *(const ull*)&Bs[k][tx*6];
            ull b1 = *(const ull*)&Bs[k][tx*6 + 2];
            ull b2 = *(const ull*)&Bs[k][tx*6 + 4];
            ull pa;
            PK2(pa, a0.x, a0.x); FMA2(acc2[0][0], pa, b0); FMA2(acc2[0][1], pa, b1); FMA2(acc2[0][2], pa, b2);
            PK2(pa, a0.y, a0.y); FMA2(acc2[1][0], pa, b0); FMA2(acc2[1][1], pa, b1); FMA2(acc2[1][2], pa, b2);
            PK2(pa, a0.z, a0.z); FMA2(acc2[2][0], pa, b0); FMA2(acc2[2][1], pa, b1); FMA2(acc2[2][2], pa, b2);
            PK2(pa, a0.w, a0.w); FMA2(acc2[3][0], pa, b0); FMA2(acc2[3][1], pa, b1); FMA2(acc2[3][2], pa, b2);
            PK2(pa, a1.x, a1.x); FMA2(acc2[4][0], pa, b0); FMA2(acc2[4][1], pa, b1); FMA2(acc2[4][2], pa, b2);
            PK2(pa, a1.y, a1.y); FMA2(acc2[5][0], pa, b0); FMA2(acc2[5][1], pa, b1); FMA2(acc2[5][2], pa, b2);
            PK2(pa, a1.z, a1.z); FMA2(acc2[6][0], pa, b0); FMA2(acc2[6][1], pa, b1); FMA2(acc2[6][2], pa, b2);
            PK2(pa, a1.w, a1.w); FMA2(acc2[7][0], pa, b0); FMA2(acc2[7][1], pa, b1); FMA2(acc2[7][2], pa, b2);
        }
        __syncthreads();
    }

    float* O = g_O + ((size_t)n*HP + row0)*CH + o0;
#pragma unroll
    for (int i = 0; i < 8; i++) {
        float v0,v1,v2,v3,v4,v5;
        UPK2(v0,v1,acc2[i][0]);
        UPK2(v2,v3,acc2[i][1]);
        UPK2(v4,v5,acc2[i][2]);
        float* orow = O + (size_t)(ty*8 + i)*CH + tx*6;
        *(float2*)&orow[0] = make_float2(v0,v1);
        *(float2*)&orow[2] = make_float2(v2,v3);
        *(float2*)&orow[4] = make_float2(v4,v5);
    }
}

// =================================================================================
// Kernel 6: final projection + residual (FFMA2).
// =================================================================================
__global__ __launch_bounds__(256) void proj_kernel(
    const float* __restrict__ x,
    const float* __restrict__ Wp,
    const float* __restrict__ bp,
    const float* __restrict__ gamma,
    float* __restrict__ out)
{
    int n  = blockIdx.z;
    int p0 = blockIdx.x * 64;
    int o0 = blockIdx.y * 64;
    const float* A = g_O + (size_t)n*HP*CH;

    __shared__ float As[32][68];
    __shared__ float Bs[32][68];

    int t  = threadIdx.x;
    int tx = t & 15, ty = t >> 4;
    ull acc2[4][2] = {};   // [oj][pixel-pair]

    for (int c0 = 0; c0 < CH; c0 += 32) {
#pragma unroll
        for (int i = 0; i < 8; i++) {
            int idx = t + i*256;
            int pix = idx >> 5, c = idx & 31;
            As[c][pix] = A[(size_t)(p0 + pix)*CH + c0 + c];
        }
#pragma unroll
        for (int i = 0; i < 8; i++) {
            int idx = t + i*256;
            int o = idx >> 5, c = idx & 31;
            int oo = o0 + o;
            Bs[c][o] = (oo < CH) ? Wp[(size_t)oo*CH + c0 + c] : 0.f;
        }
        __syncthreads();
#pragma unroll
        for (int c = 0; c < 32; c++) {
            ulonglong2 a2 = *(const ulonglong2*)&As[c][tx*4];
            float4 b = *(const float4*)&Bs[c][ty*4];
            ull pb;
            PK2(pb, b.x, b.x); FMA2(acc2[0][0], pb, a2.x); FMA2(acc2[0][1], pb, a2.y);
            PK2(pb, b.y, b.y); FMA2(acc2[1][0], pb, a2.x); FMA2(acc2[1][1], pb, a2.y);
            PK2(pb, b.z, b.z); FMA2(acc2[2][0], pb, a2.x); FMA2(acc2[2][1], pb, a2.y);
            PK2(pb, b.w, b.w); FMA2(acc2[3][0], pb, a2.x); FMA2(acc2[3][1], pb, a2.y);
        }
        __syncthreads();
    }
    float g = gamma[0];
#pragma unroll
    for (int j = 0; j < 4; j++) {
        int o = o0 + ty*4 + j;
        if (o < CH) {
            float a0,a1,a2,a3;
            UPK2(a0,a1,acc2[j][0]);
            UPK2(a2,a3,acc2[j][1]);
            float bb = bp[o];
            size_t base = (size_t)n*CH*HP + (size_t)o*HP + p0 + tx*4;
            float4 xr = *(const float4*)(x + base);
            float4 v;
            v.x = g*(a0 + bb) + xr.x;
            v.y = g*(a1 + bb) + xr.y;
            v.z = g*(a2 + bb) + xr.z;
            v.w = g*(a3 + bb) + xr.w;
            *(float4*)(out + base) = v;
        }
    }
}

// =================================================================================
extern "C" void kernel_launch(void* const* d_in, const int* in_sizes, int n_in,
                              void* d_out, int out_size)
{
    const float* x     = (const float*)d_in[0];
    const float* Wq    = (const float*)d_in[1];
    const float* Wk    = (const float*)d_in[2];
    const float* Wv    = (const float*)d_in[3];
    const float* Wx    = (const float*)d_in[4];
    const float* Wy    = (const float*)d_in[5];
    const float* Wproj = (const float*)d_in[6];
    const float* bproj = (const float*)d_in[7];
    const float* Wc    = (const float*)d_in[8];
    const float* bc    = (const float*)d_in[9];
    const float* gamma = (const float*)d_in[10];
    float* out = (float*)d_out;

    cudaFuncSetAttribute(attn_e_kernel, cudaFuncAttributeMaxDynamicSharedMemorySize,
                         AE_TOT * (int)sizeof(float));

    qkv_kernel<<<dim3(64, 5, 6), 256>>>(x, Wq, Wk, Wv);
    pf_kernel<<<dim3(2048, 2), 144>>>(Wx, Wy);
    ctx1_kernel<<<dim3(32, 2), 288>>>();
    ctx2_kernel<<<2, 288>>>(Wc, bc);
    attn_e_kernel<<<dim3(HP/TQ, NB), 512, AE_TOT * (int)sizeof(float)>>>();
    pv_kernel<<<dim3(HP/128, 3, NB), 256>>>();
    proj_kernel<<<dim3(64, 5, 2), 256>>>(x, Wproj, bproj, gamma, out);
}

// round 6
// speedup vs baseline: 1.4830x; 1.1951x over previous
#include <cuda_runtime.h>
#include <math.h>

#define NB  2
#define CH  288
#define HP  4096
#define KPP 1024
#define NH  9
#define DH  32
#define TQ  16

typedef unsigned long long ull;

// ---- packed f32x2 FMA (sm_103a FFMA2; PTX-only path) ----
#define FMA2(d, a, b) asm("fma.rn.f32x2 %0, %1, %2, %0;" : "+l"(d) : "l"(a), "l"(b))
#define PK2(d, lo, hi) asm("mov.b64 %0, {%1, %2};" : "=l"(d) : "r"(__float_as_uint(lo)), "r"(__float_as_uint(hi)))
#define UPK2(lo, hi, v) do { unsigned int _ul, _uh; \
    asm("mov.b64 {%0, %1}, %2;" : "=r"(_ul), "=r"(_uh) : "l"(v)); \
    (lo) = __uint_as_float(_ul); (hi) = __uint_as_float(_uh); } while (0)

// ---------------- device scratch ----------------
__device__ float g_Q   [NB*HP*CH];
__device__ float g_KTd [NB*NH*DH*KPP];   // k[n][m][dd][kp]
__device__ float g_V   [NB*KPP*CH];
__device__ float g_O   [NB*HP*CH];
__device__ float g_PFX [NH*64*32*DH];
__device__ float g_PFY [NH*64*32*DH];
__device__ float g_Atn [NB*HP*KPP];      // combined attention weights
__device__ float g_ctxp[NB*32*CH];
__device__ float g_mixw[NB*NH];

// =================================================================================
// Kernel 1: Q/K/V projections (FFMA2 inner).  [unchanged from passing R5]
// =================================================================================
__global__ __launch_bounds__(256) void qkv_kernel(
    const float* __restrict__ x,
    const float* __restrict__ Wq,
    const float* __restrict__ Wk,
    const float* __restrict__ Wv)
{
    int which = blockIdx.z >> 1;
    int n     = blockIdx.z & 1;
    int rows  = (which == 0) ? HP : KPP;
    int p0    = blockIdx.x * 64;
    if (p0 >= rows) return;
    int o0    = blockIdx.y * 64;

    const float* W = (which == 0) ? Wq : (which == 1 ? Wk : Wv);
    const float* xb = x + (size_t)n*CH*HP;

    __shared__ float As[32][64];
    __shared__ float Bs[32][68];

    int t  = threadIdx.x;
    int tx = t & 15, ty = t >> 4;
    ull acc2[4][2] = {};

    for (int c0 = 0; c0 < CH; c0 += 32) {
#pragma unroll
        for (int i = 0; i < 8; i++) {
            int idx = t + i*256;
            int c = idx >> 6, pix = idx & 63;
            int row = p0 + pix;
            int pixel = (which == 0) ? row : (((row >> 5) << 7) | ((row & 31) << 1));
            As[c][pix] = xb[(size_t)(c0 + c)*HP + pixel];
        }
#pragma unroll
        for (int i = 0; i < 8; i++) {
            int idx = t + i*256;
            int o = idx >> 5, c = idx & 31;
            int oo = o0 + o;
            Bs[c][o] = (oo < CH) ? W[(size_t)oo*CH + c0 + c] : 0.f;
        }
        __syncthreads();
#pragma unroll
        for (int c = 0; c < 32; c++) {
            float4 a = *(const float4*)&As[c][ty*4];
            ulonglong2 b2 = *(const ulonglong2*)&Bs[c][tx*4];
            ull pa;
            PK2(pa, a.x, a.x); FMA2(acc2[0][0], pa, b2.x); FMA2(acc2[0][1], pa, b2.y);
            PK2(pa, a.y, a.y); FMA2(acc2[1][0], pa, b2.x); FMA2(acc2[1][1], pa, b2.y);
            PK2(pa, a.z, a.z); FMA2(acc2[2][0], pa, b2.x); FMA2(acc2[2][1], pa, b2.y);
            PK2(pa, a.w, a.w); FMA2(acc2[3][0], pa, b2.x); FMA2(acc2[3][1], pa, b2.y);
        }
        __syncthreads();
    }
    float acc[4][4];
#pragma unroll
    for (int i = 0; i < 4; i++) {
        UPK2(acc[i][0], acc[i][1], acc2[i][0]);
        UPK2(acc[i][2], acc[i][3], acc2[i][1]);
    }
    int o = o0 + tx*4;
    if (o >= CH) return;

    if (which == 1) {
#pragma unroll
        for (int i = 0; i < 4; i++) {
            int row = p0 + ty*4 + i;
#pragma unroll
            for (int c = 0; c < 4; c++) {
                int oo = o + c;
                g_KTd[(((size_t)n*NH + (oo >> 5))*DH + (oo & 31))*KPP + row] = acc[i][c];
            }
        }
    } else {
        float* out = (which == 0) ? (g_Q + (size_t)n*HP*CH) : (g_V + (size_t)n*KPP*CH);
#pragma unroll
        for (int i = 0; i < 4; i++) {
            int row = p0 + ty*4 + i;
            *(float4*)&out[(size_t)row*CH + o] =
                make_float4(acc[i][0], acc[i][1], acc[i][2], acc[i][3]);
        }
    }
}

// =================================================================================
// Kernel 2: positional factor tables.  [unchanged]
// =================================================================================
__global__ void pf_kernel(const float* __restrict__ Wx, const float* __restrict__ Wy)
{
    int a = blockIdx.x >> 5;
    int b = blockIdx.x & 31;
    const float* W = blockIdx.y ? Wy : Wx;
    float* out = blockIdx.y ? g_PFY : g_PFX;

    __shared__ float emb[144];
    int t = threadIdx.x;
    float diff = (float)a - 2.0f*(float)b;
    if (t < 72) {
        float dm  = powf(1000.0f, (4.0f/288.0f)*(float)t);
        float arg = diff / dm;
        emb[t]      = sinf(arg);
        emb[72 + t] = cosf(arg);
    }
    __syncthreads();
    const float inv_sqrt2 = 0.7071067811865476f;
    for (int j = t; j < CH; j += 144) {
        float s = 0.f;
        const float* wr = W + (size_t)j*144;
#pragma unroll 8
        for (int f = 0; f < 144; f++) s += emb[f]*wr[f];
        int m = j >> 5, dd = j & 31;
        out[(((size_t)m*64 + a)*32 + b)*32 + dd] = s * inv_sqrt2;
    }
}

// =================================================================================
// Kernel 3a/3b: context mean (two-stage) + head-mix softmax.  [unchanged]
// =================================================================================
__global__ __launch_bounds__(288) void ctx1_kernel()
{
    int n = blockIdx.y, b = blockIdx.x, t = threadIdx.x;
    const float* q = g_Q + ((size_t)n*HP + b*128)*CH + t;
    float s = 0.f;
#pragma unroll 8
    for (int p = 0; p < 128; p++) s += q[(size_t)p*CH];
    g_ctxp[((size_t)n*32 + b)*CH + t] = s;
}

__global__ __launch_bounds__(288) void ctx2_kernel(const float* __restrict__ Wc,
                                                   const float* __restrict__ bc)
{
    int n = blockIdx.x, t = threadIdx.x;
    __shared__ float cs[CH];
    __shared__ float lg[NH];
    float s = 0.f;
#pragma unroll
    for (int b = 0; b < 32; b++) s += g_ctxp[((size_t)n*32 + b)*CH + t];
    cs[t] = s * (1.0f/HP);
    __syncthreads();
    if (t < NH) {
        float l = bc[t];
        const float* wr = Wc + (size_t)t*CH;
#pragma unroll 8
        for (int o = 0; o < CH; o++) l += cs[o]*wr[o];
        lg[t] = l;
    }
    __syncthreads();
    if (t == 0) {
        float mx = lg[0];
        for (int j = 1; j < NH; j++) mx = fmaxf(mx, lg[j]);
        float e[NH], sum = 0.f;
        for (int j = 0; j < NH; j++) { e[j] = expf(lg[j]-mx); sum += e[j]; }
        for (int j = 0; j < NH; j++) g_mixw[n*NH + j] = e[j]/sum;
    }
}

// =================================================================================
// Kernel 4 (REWORKED): attention energies + softmax + head mix -> g_Atn.
// 256 threads, 8 warps. Thread tile: 8 queries x 8 keys (4 keys in each 512-half).
// K for the whole head resident in smem (32 x 1024). Q reads are warp-uniform
// broadcasts. acc in 32 packed-f32x2 chains.
// =================================================================================
#define AE_QS  0
#define AE_KS  (16*CH)                 // 4608
#define AE_EX  (AE_KS + 32*1024)       // +32768
#define AE_EY  (AE_EX + 512)
#define AE_RD  (AE_EY + 512)
#define AE_TOT (AE_RD + 128)           // 38528 floats = 154,112 B

__global__ __launch_bounds__(256, 1) void attn_e_kernel()
{
    extern __shared__ float sm[];
    float* Qs  = sm + AE_QS;
    float* Ks  = sm + AE_KS;
    float* exs = sm + AE_EX;
    float* eys = sm + AE_EY;
    float* red = sm + AE_RD;

    int n  = blockIdx.y;
    int q0 = blockIdx.x * TQ;
    int h  = q0 >> 6;
    int wbase = q0 & 63;
    int t  = threadIdx.x;
    int warp = t >> 5, lane = t & 31;

    // load Q tile (16 x 288 = 1152 float4)
    {
        const float4* src = (const float4*)(g_Q + ((size_t)n*HP + q0)*CH);
        float4* dst = (float4*)Qs;
#pragma unroll
        for (int i = 0; i < 5; i++) {
            int idx = t + i*256;
            if (idx < 1152) dst[idx] = src[idx];
        }
    }

    const int kt   = t & 127;        // key-thread within group
    const int kqA  = kt * 4;         // 4 keys in first half; second half at 512+kqA
    const int grp  = t >> 7;         // query group (0/1), 8 queries each
    const int qb   = grp * 8;
    const int wgrp = warp & 3;       // warp within group

    const int wkA = kqA & 31;        // w-bias index (same for both halves)
    const int hkA = kqA >> 5;        // h-bias index, first half; second = hkA+16

    float ab[8][8] = {};

    for (int m = 0; m < NH; m++) {
        float mw = g_mixw[n*NH + m];

        __syncthreads();   // (A) prior readers of exs/Ks/red done; Q visible at m=0

        // ---- bias dots: 512 (qi,kk) pairs, 2 per thread ----
#pragma unroll
        for (int r = 0; r < 2; r++) {
            int e  = t + r*256;
            int qi = e >> 5, kk = e & 31;
            const float* qp = Qs + qi*CH + m*DH;
            const float* px = g_PFX + (((size_t)m*64 + wbase + qi)*32 + kk)*32;
            const float* py = g_PFY + (((size_t)m*64 + h)*32 + kk)*32;
            float sx = 0.f, sy = 0.f;
#pragma unroll
            for (int d = 0; d < DH; d++) {
                float qv = qp[d];
                sx += qv * px[d];
                sy += qv * py[d];
            }
            exs[e] = sx; eys[e] = sy;
        }

        // ---- stage full K head: 32 rows x 256 float4 ----
        {
            const float* kb = g_KTd + (((size_t)n*NH + m)*DH)*KPP;
#pragma unroll
            for (int dd = 0; dd < 32; dd++) {
                ((float4*)(Ks + dd*1024))[t] = ((const float4*)(kb + (size_t)dd*KPP))[t];
            }
        }
        __syncthreads();   // (B)

        // ---- QK: 8q x 8k per thread, packed f32x2 ----
        ull acc2[8][4] = {};
#pragma unroll
        for (int d4 = 0; d4 < 8; d4++) {
            const float* kbase = Ks + (d4*4)*1024;
            ulonglong2 kA0 = *(const ulonglong2*)(kbase          + kqA);
            ulonglong2 kA1 = *(const ulonglong2*)(kbase + 1024   + kqA);
            ulonglong2 kA2 = *(const ulonglong2*)(kbase + 2048   + kqA);
            ulonglong2 kA3 = *(const ulonglong2*)(kbase + 3072   + kqA);
            ulonglong2 kB0 = *(const ulonglong2*)(kbase + 512    + kqA);
            ulonglong2 kB1 = *(const ulonglong2*)(kbase + 1536   + kqA);
            ulonglong2 kB2 = *(const ulonglong2*)(kbase + 2560   + kqA);
            ulonglong2 kB3 = *(const ulonglong2*)(kbase + 3584   + kqA);
#pragma unroll
            for (int u = 0; u < 8; u++) {
                float4 qq = *(const float4*)&Qs[(qb+u)*CH + m*DH + d4*4];  // broadcast
                ull pa;
                PK2(pa, qq.x, qq.x);
                FMA2(acc2[u][0], pa, kA0.x); FMA2(acc2[u][1], pa, kA0.y);
                FMA2(acc2[u][2], pa, kB0.x); FMA2(acc2[u][3], pa, kB0.y);
                PK2(pa, qq.y, qq.y);
                FMA2(acc2[u][0], pa, kA1.x); FMA2(acc2[u][1], pa, kA1.y);
                FMA2(acc2[u][2], pa, kB1.x); FMA2(acc2[u][3], pa, kB1.y);
                PK2(pa, qq.z, qq.z);
                FMA2(acc2[u][0], pa, kA2.x); FMA2(acc2[u][1], pa, kA2.y);
                FMA2(acc2[u][2], pa, kB2.x); FMA2(acc2[u][3], pa, kB2.y);
                PK2(pa, qq.w, qq.w);
                FMA2(acc2[u][0], pa, kA3.x); FMA2(acc2[u][1], pa, kA3.y);
                FMA2(acc2[u][2], pa, kB3.x); FMA2(acc2[u][3], pa, kB3.y);
            }
        }

        // ---- bias add into e[8][8] ----
        float e[8][8];
#pragma unroll
        for (int u = 0; u < 8; u++) {
            int qi = qb + u;
            float4 ex4 = *(const float4*)&exs[qi*32 + wkA];
            float eyA  = eys[qi*32 + hkA];
            float eyB  = eys[qi*32 + hkA + 16];
            float a0,a1,a2,a3;
            UPK2(a0,a1,acc2[u][0]); UPK2(a2,a3,acc2[u][1]);
            e[u][0] = a0 + ex4.x + eyA;
            e[u][1] = a1 + ex4.y + eyA;
            e[u][2] = a2 + ex4.z + eyA;
            e[u][3] = a3 + ex4.w + eyA;
            UPK2(a0,a1,acc2[u][2]); UPK2(a2,a3,acc2[u][3]);
            e[u][4] = a0 + ex4.x + eyB;
            e[u][5] = a1 + ex4.y + eyB;
            e[u][6] = a2 + ex4.z + eyB;
            e[u][7] = a3 + ex4.w + eyB;
        }

        // ---- softmax over 1024 keys (128 threads = 4 warps per query group) ----
        float mx[8];
#pragma unroll
        for (int u = 0; u < 8; u++) {
            float v = e[u][0];
#pragma unroll
            for (int j = 1; j < 8; j++) v = fmaxf(v, e[u][j]);
#pragma unroll
            for (int s2 = 16; s2; s2 >>= 1) v = fmaxf(v, __shfl_xor_sync(0xffffffffu, v, s2));
            mx[u] = v;
        }
        if (lane == 0) {
#pragma unroll
            for (int u = 0; u < 8; u++) red[grp*32 + wgrp*8 + u] = mx[u];
        }
        __syncthreads();   // (C)
#pragma unroll
        for (int u = 0; u < 8; u++) {
            float v = red[grp*32 + u];
            v = fmaxf(v, red[grp*32 + 8  + u]);
            v = fmaxf(v, red[grp*32 + 16 + u]);
            v = fmaxf(v, red[grp*32 + 24 + u]);
            mx[u] = v;
        }
        float sme[8];
#pragma unroll
        for (int u = 0; u < 8; u++) {
            float s = 0.f;
#pragma unroll
            for (int j = 0; j < 8; j++) {
                float p = __expf(e[u][j] - mx[u]);
                e[u][j] = p;
                s += p;
            }
#pragma unroll
            for (int s2 = 16; s2; s2 >>= 1) s += __shfl_xor_sync(0xffffffffu, s, s2);
            sme[u] = s;
        }
        if (lane == 0) {
#pragma unroll
            for (int u = 0; u < 8; u++) red[64 + grp*32 + wgrp*8 + u] = sme[u];
        }
        __syncthreads();   // (D)
#pragma unroll
        for (int u = 0; u < 8; u++) {
            float s = red[64 + grp*32 + u] + red[64 + grp*32 + 8 + u]
                    + red[64 + grp*32 + 16 + u] + red[64 + grp*32 + 24 + u];
            float sc = mw / s;
#pragma unroll
            for (int j = 0; j < 8; j++) ab[u][j] += e[u][j] * sc;
        }
    }

    // ---- write combined attention ----
#pragma unroll
    for (int u = 0; u < 8; u++) {
        float* arow = g_Atn + ((size_t)n*HP + q0 + qb + u)*KPP;
        *(float4*)&arow[kqA]       = make_float4(ab[u][0], ab[u][1], ab[u][2], ab[u][3]);
        *(float4*)&arow[512 + kqA] = make_float4(ab[u][4], ab[u][5], ab[u][6], ab[u][7]);
    }
}

// =================================================================================
// Kernel 5: PV GEMM.  [unchanged from passing R5]
// =================================================================================
__global__ __launch_bounds__(256) void pv_kernel()
{
    int n    = blockIdx.z;
    int row0 = blockIdx.x * 128;
    int o0   = blockIdx.y * 96;

    __shared__ float As[16][132];
    __shared__ float Bs[16][96];

    int t  = threadIdx.x;
    int tx = t & 15, ty = t >> 4;

    const float* A = g_Atn + ((size_t)n*HP + row0)*KPP;
    const float* V = g_V + (size_t)n*KPP*CH + o0;

    ull acc2[8][3] = {};

    for (int k0 = 0; k0 < KPP; k0 += 16) {
#pragma unroll
        for (int i = 0; i < 8; i++) {
            int e = t + i*256;
            int row = e >> 4, k = e & 15;
            As[k][row] = A[(size_t)row*KPP + k0 + k];
        }
#pragma unroll
        for (int i = 0; i < 6; i++) {
            int e = t + i*256;
            int k = e / 96, col = e % 96;
            Bs[k][col] = V[(size_t)(k0 + k)*CH + col];
        }
        __syncthreads();
#pragma unroll
        for (int k = 0; k < 16; k++) {
            float4 a0 = *(const float4*)&As[k][ty*8];
            float4 a1 = *(const float4*)&As[k][ty*8 + 4];
            ull b0 = *(const ull*)&Bs[k][tx*6];
            ull b1 = *(const ull*)&Bs[k][tx*6 + 2];
            ull b2 = *(const ull*)&Bs[k][tx*6 + 4];
            ull pa;
            PK2(pa, a0.x, a0.x); FMA2(acc2[0][0], pa, b0); FMA2(acc2[0][1], pa, b1); FMA2(acc2[0][2], pa, b2);
            PK2(pa, a0.y, a0.y); FMA2(acc2[1][0], pa, b0); FMA2(acc2[1][1], pa, b1); FMA2(acc2[1][2], pa, b2);
            PK2(pa, a0.z, a0.z); FMA2(acc2[2][0], pa, b0); FMA2(acc2[2][1], pa, b1); FMA2(acc2[2][2], pa, b2);
            PK2(pa, a0.w, a0.w); FMA2(acc2[3][0], pa, b0); FMA2(acc2[3][1], pa, b1); FMA2(acc2[3][2], pa, b2);
            PK2(pa, a1.x, a1.x); FMA2(acc2[4][0], pa, b0); FMA2(acc2[4][1], pa, b1); FMA2(acc2[4][2], pa, b2);
            PK2(pa, a1.y, a1.y); FMA2(acc2[5][0], pa, b0); FMA2(acc2[5][1], pa, b1); FMA2(acc2[5][2], pa, b2);
            PK2(pa, a1.z, a1.z); FMA2(acc2[6][0], pa, b0); FMA2(acc2[6][1], pa, b1); FMA2(acc2[6][2], pa, b2);
            PK2(pa, a1.w, a1.w); FMA2(acc2[7][0], pa, b0); FMA2(acc2[7][1], pa, b1); FMA2(acc2[7][2], pa, b2);
        }
        __syncthreads();
    }

    float* O = g_O + ((size_t)n*HP + row0)*CH + o0;
#pragma unroll
    for (int i = 0; i < 8; i++) {
        float v0,v1,v2,v3,v4,v5;
        UPK2(v0,v1,acc2[i][0]);
        UPK2(v2,v3,acc2[i][1]);
        UPK2(v4,v5,acc2[i][2]);
        float* orow = O + (size_t)(ty*8 + i)*CH + tx*6;
        *(float2*)&orow[0] = make_float2(v0,v1);
        *(float2*)&orow[2] = make_float2(v2,v3);
        *(float2*)&orow[4] = make_float2(v4,v5);
    }
}

// =================================================================================
// Kernel 6: final projection + residual (FFMA2).  [unchanged from passing R5]
// =================================================================================
__global__ __launch_bounds__(256) void proj_kernel(
    const float* __restrict__ x,
    const float* __restrict__ Wp,
    const float* __restrict__ bp,
    const float* __restrict__ gamma,
    float* __restrict__ out)
{
    int n  = blockIdx.z;
    int p0 = blockIdx.x * 64;
    int o0 = blockIdx.y * 64;
    const float* A = g_O + (size_t)n*HP*CH;

    __shared__ float As[32][68];
    __shared__ float Bs[32][68];

    int t  = threadIdx.x;
    int tx = t & 15, ty = t >> 4;
    ull acc2[4][2] = {};

    for (int c0 = 0; c0 < CH; c0 += 32) {
#pragma unroll
        for (int i = 0; i < 8; i++) {
            int idx = t + i*256;
            int pix = idx >> 5, c = idx & 31;
            As[c][pix] = A[(size_t)(p0 + pix)*CH + c0 + c];
        }
#pragma unroll
        for (int i = 0; i < 8; i++) {
            int idx = t + i*256;
            int o = idx >> 5, c = idx & 31;
            int oo = o0 + o;
            Bs[c][o] = (oo < CH) ? Wp[(size_t)oo*CH + c0 + c] : 0.f;
        }
        __syncthreads();
#pragma unroll
        for (int c = 0; c < 32; c++) {
            ulonglong2 a2 = *(const ulonglong2*)&As[c][tx*4];
            float4 b = *(const float4*)&Bs[c][ty*4];
            ull pb;
            PK2(pb, b.x, b.x); FMA2(acc2[0][0], pb, a2.x); FMA2(acc2[0][1], pb, a2.y);
            PK2(pb, b.y, b.y); FMA2(acc2[1][0], pb, a2.x); FMA2(acc2[1][1], pb, a2.y);
            PK2(pb, b.z, b.z); FMA2(acc2[2][0], pb, a2.x); FMA2(acc2[2][1], pb, a2.y);
            PK2(pb, b.w, b.w); FMA2(acc2[3][0], pb, a2.x); FMA2(acc2[3][1], pb, a2.y);
        }
        __syncthreads();
    }
    float g = gamma[0];
#pragma unroll
    for (int j = 0; j < 4; j++) {
        int o = o0 + ty*4 + j;
        if (o < CH) {
            float a0,a1,a2,a3;
            UPK2(a0,a1,acc2[j][0]);
            UPK2(a2,a3,acc2[j][1]);
            float bb = bp[o];
            size_t base = (size_t)n*CH*HP + (size_t)o*HP + p0 + tx*4;
            float4 xr = *(const float4*)(x + base);
            float4 v;
            v.x = g*(a0 + bb) + xr.x;
            v.y = g*(a1 + bb) + xr.y;
            v.z = g*(a2 + bb) + xr.z;
            v.w = g*(a3 + bb) + xr.w;
            *(float4*)(out + base) = v;
        }
    }
}

// =================================================================================
extern "C" void kernel_launch(void* const* d_in, const int* in_sizes, int n_in,
                              void* d_out, int out_size)
{
    const float* x     = (const float*)d_in[0];
    const float* Wq    = (const float*)d_in[1];
    const float* Wk    = (const float*)d_in[2];
    const float* Wv    = (const float*)d_in[3];
    const float* Wx    = (const float*)d_in[4];
    const float* Wy    = (const float*)d_in[5];
    const float* Wproj = (const float*)d_in[6];
    const float* bproj = (const float*)d_in[7];
    const float* Wc    = (const float*)d_in[8];
    const float* bc    = (const float*)d_in[9];
    const float* gamma = (const float*)d_in[10];
    float* out = (float*)d_out;

    cudaFuncSetAttribute(attn_e_kernel, cudaFuncAttributeMaxDynamicSharedMemorySize,
                         AE_TOT * (int)sizeof(float));

    qkv_kernel<<<dim3(64, 5, 6), 256>>>(x, Wq, Wk, Wv);
    pf_kernel<<<dim3(2048, 2), 144>>>(Wx, Wy);
    ctx1_kernel<<<dim3(32, 2), 288>>>();
    ctx2_kernel<<<2, 288>>>(Wc, bc);
    attn_e_kernel<<<dim3(HP/TQ, NB), 256, AE_TOT * (int)sizeof(float)>>>();
    pv_kernel<<<dim3(HP/128, 3, NB), 256>>>();
    proj_kernel<<<dim3(64, 5, 2), 256>>>(x, Wproj, bproj, gamma, out);
}

// round 8
// speedup vs baseline: 1.5294x; 1.0313x over previous
#include <cuda_runtime.h>
#include <math.h>

#define NB  2
#define CH  288
#define HP  4096
#define KPP 1024
#define NH  9
#define DH  32
#define TQ  16

typedef unsigned long long ull;

// ---- packed f32x2 FMA (sm_103a FFMA2; PTX-only path) ----
#define FMA2(d, a, b) asm("fma.rn.f32x2 %0, %1, %2, %0;" : "+l"(d) : "l"(a), "l"(b))
#define PK2(d, lo, hi) asm("mov.b64 %0, {%1, %2};" : "=l"(d) : "r"(__float_as_uint(lo)), "r"(__float_as_uint(hi)))
#define UPK2(lo, hi, v) do { unsigned int _ul, _uh; \
    asm("mov.b64 {%0, %1}, %2;" : "=r"(_ul), "=r"(_uh) : "l"(v)); \
    (lo) = __uint_as_float(_ul); (hi) = __uint_as_float(_uh); } while (0)

// ---- cp.async helpers ----
#define CP_ASYNC16(dst_u32, src_ptr) \
    asm volatile("cp.async.cg.shared.global [%0], [%1], 16;" :: "r"(dst_u32), "l"(src_ptr))
#define CP_COMMIT() asm volatile("cp.async.commit_group;")
#define CP_WAIT(n)  asm volatile("cp.async.wait_group %0;" :: "n"(n))

// ---------------- device scratch ----------------
__device__ float g_Q   [NB*HP*CH];
__device__ float g_KTd [NB*NH*DH*KPP];   // k[n][m][dd][kp]
__device__ float g_V   [NB*KPP*CH];
__device__ float g_O   [NB*HP*CH];
__device__ float g_PFX [NH*64*32*DH];
__device__ float g_PFY [NH*64*32*DH];
__device__ float g_Atn [NB*HP*KPP];      // combined attention weights
__device__ float g_ctxp[NB*32*CH];

// =================================================================================
// Kernel 1: Q/K/V projections (FFMA2 inner).  [unchanged]
// =================================================================================
__global__ __launch_bounds__(256) void qkv_kernel(
    const float* __restrict__ x,
    const float* __restrict__ Wq,
    const float* __restrict__ Wk,
    const float* __restrict__ Wv)
{
    int which = blockIdx.z >> 1;
    int n     = blockIdx.z & 1;
    int rows  = (which == 0) ? HP : KPP;
    int p0    = blockIdx.x * 64;
    if (p0 >= rows) return;
    int o0    = blockIdx.y * 64;

    const float* W = (which == 0) ? Wq : (which == 1 ? Wk : Wv);
    const float* xb = x + (size_t)n*CH*HP;

    __shared__ float As[32][64];
    __shared__ float Bs[32][68];

    int t  = threadIdx.x;
    int tx = t & 15, ty = t >> 4;
    ull acc2[4][2] = {};

    for (int c0 = 0; c0 < CH; c0 += 32) {
#pragma unroll
        for (int i = 0; i < 8; i++) {
            int idx = t + i*256;
            int c = idx >> 6, pix = idx & 63;
            int row = p0 + pix;
            int pixel = (which == 0) ? row : (((row >> 5) << 7) | ((row & 31) << 1));
            As[c][pix] = xb[(size_t)(c0 + c)*HP + pixel];
        }
#pragma unroll
        for (int i = 0; i < 8; i++) {
            int idx = t + i*256;
            int o = idx >> 5, c = idx & 31;
            int oo = o0 + o;
            Bs[c][o] = (oo < CH) ? W[(size_t)oo*CH + c0 + c] : 0.f;
        }
        __syncthreads();
#pragma unroll
        for (int c = 0; c < 32; c++) {
            float4 a = *(const float4*)&As[c][ty*4];
            ulonglong2 b2 = *(const ulonglong2*)&Bs[c][tx*4];
            ull pa;
            PK2(pa, a.x, a.x); FMA2(acc2[0][0], pa, b2.x); FMA2(acc2[0][1], pa, b2.y);
            PK2(pa, a.y, a.y); FMA2(acc2[1][0], pa, b2.x); FMA2(acc2[1][1], pa, b2.y);
            PK2(pa, a.z, a.z); FMA2(acc2[2][0], pa, b2.x); FMA2(acc2[2][1], pa, b2.y);
            PK2(pa, a.w, a.w); FMA2(acc2[3][0], pa, b2.x); FMA2(acc2[3][1], pa, b2.y);
        }
        __syncthreads();
    }
    float acc[4][4];
#pragma unroll
    for (int i = 0; i < 4; i++) {
        UPK2(acc[i][0], acc[i][1], acc2[i][0]);
        UPK2(acc[i][2], acc[i][3], acc2[i][1]);
    }
    int o = o0 + tx*4;
    if (o >= CH) return;

    if (which == 1) {
#pragma unroll
        for (int i = 0; i < 4; i++) {
            int row = p0 + ty*4 + i;
#pragma unroll
            for (int c = 0; c < 4; c++) {
                int oo = o + c;
                g_KTd[(((size_t)n*NH + (oo >> 5))*DH + (oo & 31))*KPP + row] = acc[i][c];
            }
        }
    } else {
        float* out = (which == 0) ? (g_Q + (size_t)n*HP*CH) : (g_V + (size_t)n*KPP*CH);
#pragma unroll
        for (int i = 0; i < 4; i++) {
            int row = p0 + ty*4 + i;
            *(float4*)&out[(size_t)row*CH + o] =
                make_float4(acc[i][0], acc[i][1], acc[i][2], acc[i][3]);
        }
    }
}

// =================================================================================
// Kernel 2: positional factor tables.  [unchanged]
// =================================================================================
__global__ void pf_kernel(const float* __restrict__ Wx, const float* __restrict__ Wy)
{
    int a = blockIdx.x >> 5;
    int b = blockIdx.x & 31;
    const float* W = blockIdx.y ? Wy : Wx;
    float* out = blockIdx.y ? g_PFY : g_PFX;

    __shared__ float emb[144];
    int t = threadIdx.x;
    float diff = (float)a - 2.0f*(float)b;
    if (t < 72) {
        float dm  = powf(1000.0f, (4.0f/288.0f)*(float)t);
        float arg = diff / dm;
        emb[t]      = sinf(arg);
        emb[72 + t] = cosf(arg);
    }
    __syncthreads();
    const float inv_sqrt2 = 0.7071067811865476f;
    for (int j = t; j < CH; j += 144) {
        float s = 0.f;
        const float* wr = W + (size_t)j*144;
#pragma unroll 8
        for (int f = 0; f < 144; f++) s += emb[f]*wr[f];
        int m = j >> 5, dd = j & 31;
        out[(((size_t)m*64 + a)*32 + b)*32 + dd] = s * inv_sqrt2;
    }
}

// =================================================================================
// Kernel 3: context partial sums.  [unchanged]
// =================================================================================
__global__ __launch_bounds__(288) void ctx1_kernel()
{
    int n = blockIdx.y, b = blockIdx.x, t = threadIdx.x;
    const float* q = g_Q + ((size_t)n*HP + b*128)*CH + t;
    float s = 0.f;
#pragma unroll 8
    for (int p = 0; p < 128; p++) s += q[(size_t)p*CH];
    g_ctxp[((size_t)n*32 + b)*CH + t] = s;
}

// =================================================================================
// Kernel 4: attention.  256 threads, 8q x 8k per thread, cp.async double-buffered
// K staging, in-block mixw.  FIX vs R7: cs[] filled with a strided loop (CH=288
// > 256 threads; the guarded write left cs[256..287] uninitialized).
// =================================================================================
#define AE_QS  0
#define AE_K0  4608
#define AE_K1  (AE_K0 + 16*1024)
#define AE_EX  (AE_K1 + 16*1024)
#define AE_EY  (AE_EX + 512)
#define AE_RD  (AE_EY + 512)
#define AE_CS  (AE_RD + 128)
#define AE_MX  (AE_CS + 288)
#define AE_TOT (AE_MX + 16)          // 38832 floats = 155,328 B

__device__ __forceinline__ void stage_half(float* buf, const float* kb, int t)
{
    unsigned int dst = (unsigned int)__cvta_generic_to_shared(buf);
#pragma unroll
    for (int i = 0; i < 16; i++) {
        int idx = t + i*256;
        int row = idx >> 8, c4 = (idx & 255)*4;
        CP_ASYNC16(dst + (unsigned int)(row*1024 + c4)*4u, kb + (size_t)row*KPP + c4);
    }
    CP_COMMIT();
}

__global__ __launch_bounds__(256, 1) void attn_e_kernel(
    const float* __restrict__ Wc, const float* __restrict__ bc)
{
    extern __shared__ float sm[];
    float* Qs   = sm + AE_QS;
    float* K0   = sm + AE_K0;
    float* K1   = sm + AE_K1;
    float* exs  = sm + AE_EX;
    float* eys  = sm + AE_EY;
    float* red  = sm + AE_RD;
    float* cs   = sm + AE_CS;
    float* mixs = sm + AE_MX;

    int n  = blockIdx.y;
    int q0 = blockIdx.x * TQ;
    int h  = q0 >> 6;
    int wbase = q0 & 63;
    int t  = threadIdx.x;
    int warp = t >> 5, lane = t & 31;

    const float* khead = g_KTd + ((size_t)n*NH)*DH*KPP;

    // ---- prefetch head 0 (both halves) ----
    stage_half(K0, khead, t);
    stage_half(K1, khead + 16*KPP, t);

    // ---- mixw: finish context reduction in-block (strided: CH > blockDim) ----
    for (int c = t; c < CH; c += 256) {
        float s = 0.f;
#pragma unroll
        for (int b = 0; b < 32; b++) s += g_ctxp[((size_t)n*32 + b)*CH + c];
        cs[c] = s * (1.0f/HP);
    }

    // ---- load Q tile (16 x 288 = 1152 float4) ----
    {
        const float4* src = (const float4*)(g_Q + ((size_t)n*HP + q0)*CH);
        float4* dst = (float4*)Qs;
#pragma unroll
        for (int i = 0; i < 5; i++) {
            int idx = t + i*256;
            if (idx < 1152) dst[idx] = src[idx];
        }
    }
    __syncthreads();
    if (t < NH) {
        float l = bc[t];
        const float* wr = Wc + (size_t)t*CH;
#pragma unroll 8
        for (int o = 0; o < CH; o++) l += cs[o]*wr[o];
        mixs[t] = l;
    }
    __syncthreads();
    if (t == 0) {
        float mx = mixs[0];
        for (int j = 1; j < NH; j++) mx = fmaxf(mx, mixs[j]);
        float sum = 0.f;
        for (int j = 0; j < NH; j++) { float e2 = expf(mixs[j]-mx); mixs[j] = e2; sum += e2; }
        float inv = 1.0f/sum;
        for (int j = 0; j < NH; j++) mixs[j] *= inv;
    }

    const int kt   = t & 127;
    const int kqA  = kt * 4;
    const int grp  = t >> 7;
    const int qb   = grp * 8;
    const int wgrp = warp & 3;

    const int wkA = kqA & 31;
    const int hkA = kqA >> 5;

    float ab[8][8] = {};

    for (int m = 0; m < NH; m++) {
        // ---- wait half A of head m; barrier also covers mixs/Q/exs reuse ----
        CP_WAIT(1);
        __syncthreads();   // (1)

        float mw = mixs[m];

        // ---- bias dots (2 per thread) ----
#pragma unroll
        for (int r = 0; r < 2; r++) {
            int e  = t + r*256;
            int qi = e >> 5, kk = e & 31;
            const float* qp = Qs + qi*CH + m*DH;
            const float* px = g_PFX + (((size_t)m*64 + wbase + qi)*32 + kk)*32;
            const float* py = g_PFY + (((size_t)m*64 + h)*32 + kk)*32;
            float sx = 0.f, sy = 0.f;
#pragma unroll
            for (int d = 0; d < DH; d++) {
                float qv = qp[d];
                sx += qv * px[d];
                sy += qv * py[d];
            }
            exs[e] = sx; eys[e] = sy;
        }

        ull acc2[8][4] = {};

        // ---- QK half A (d = 0..15) ----
#pragma unroll
        for (int d4 = 0; d4 < 4; d4++) {
            const float* kbase = K0 + (d4*4)*1024;
            ulonglong2 kA0 = *(const ulonglong2*)(kbase          + kqA);
            ulonglong2 kA1 = *(const ulonglong2*)(kbase + 1024   + kqA);
            ulonglong2 kA2 = *(const ulonglong2*)(kbase + 2048   + kqA);
            ulonglong2 kA3 = *(const ulonglong2*)(kbase + 3072   + kqA);
            ulonglong2 kB0 = *(const ulonglong2*)(kbase + 512    + kqA);
            ulonglong2 kB1 = *(const ulonglong2*)(kbase + 1536   + kqA);
            ulonglong2 kB2 = *(const ulonglong2*)(kbase + 2560   + kqA);
            ulonglong2 kB3 = *(const ulonglong2*)(kbase + 3584   + kqA);
#pragma unroll
            for (int u = 0; u < 8; u++) {
                float4 qq = *(const float4*)&Qs[(qb+u)*CH + m*DH + d4*4];
                ull pa;
                PK2(pa, qq.x, qq.x);
                FMA2(acc2[u][0], pa, kA0.x); FMA2(acc2[u][1], pa, kA0.y);
                FMA2(acc2[u][2], pa, kB0.x); FMA2(acc2[u][3], pa, kB0.y);
                PK2(pa, qq.y, qq.y);
                FMA2(acc2[u][0], pa, kA1.x); FMA2(acc2[u][1], pa, kA1.y);
                FMA2(acc2[u][2], pa, kB1.x); FMA2(acc2[u][3], pa, kB1.y);
                PK2(pa, qq.z, qq.z);
                FMA2(acc2[u][0], pa, kA2.x); FMA2(acc2[u][1], pa, kA2.y);
                FMA2(acc2[u][2], pa, kB2.x); FMA2(acc2[u][3], pa, kB2.y);
                PK2(pa, qq.w, qq.w);
                FMA2(acc2[u][0], pa, kA3.x); FMA2(acc2[u][1], pa, kA3.y);
                FMA2(acc2[u][2], pa, kB3.x); FMA2(acc2[u][3], pa, kB3.y);
            }
        }
        __syncthreads();   // (2) done reading K0
        if (m < NH-1) stage_half(K0, khead + (size_t)(m+1)*DH*KPP, t);

        if (m < NH-1) { CP_WAIT(1); } else { CP_WAIT(0); }
        __syncthreads();   // (3) K1 ready

        // ---- QK half B (d = 16..31) ----
#pragma unroll
        for (int d4 = 0; d4 < 4; d4++) {
            const float* kbase = K1 + (d4*4)*1024;
            ulonglong2 kA0 = *(const ulonglong2*)(kbase          + kqA);
            ulonglong2 kA1 = *(const ulonglong2*)(kbase + 1024   + kqA);
            ulonglong2 kA2 = *(const ulonglong2*)(kbase + 2048   + kqA);
            ulonglong2 kA3 = *(const ulonglong2*)(kbase + 3072   + kqA);
            ulonglong2 kB0 = *(const ulonglong2*)(kbase + 512    + kqA);
            ulonglong2 kB1 = *(const ulonglong2*)(kbase + 1536   + kqA);
            ulonglong2 kB2 = *(const ulonglong2*)(kbase + 2560   + kqA);
            ulonglong2 kB3 = *(const ulonglong2*)(kbase + 3584   + kqA);
#pragma unroll
            for (int u = 0; u < 8; u++) {
                float4 qq = *(const float4*)&Qs[(qb+u)*CH + m*DH + 16 + d4*4];
                ull pa;
                PK2(pa, qq.x, qq.x);
                FMA2(acc2[u][0], pa, kA0.x); FMA2(acc2[u][1], pa, kA0.y);
                FMA2(acc2[u][2], pa, kB0.x); FMA2(acc2[u][3], pa, kB0.y);
                PK2(pa, qq.y, qq.y);
                FMA2(acc2[u][0], pa, kA1.x); FMA2(acc2[u][1], pa, kA1.y);
                FMA2(acc2[u][2], pa, kB1.x); FMA2(acc2[u][3], pa, kB1.y);
                PK2(pa, qq.z, qq.z);
                FMA2(acc2[u][0], pa, kA2.x); FMA2(acc2[u][1], pa, kA2.y);
                FMA2(acc2[u][2], pa, kB2.x); FMA2(acc2[u][3], pa, kB2.y);
                PK2(pa, qq.w, qq.w);
                FMA2(acc2[u][0], pa, kA3.x); FMA2(acc2[u][1], pa, kA3.y);
                FMA2(acc2[u][2], pa, kB3.x); FMA2(acc2[u][3], pa, kB3.y);
            }
        }
        __syncthreads();   // (4) done reading K1; exs/eys visible
        if (m < NH-1) stage_half(K1, khead + ((size_t)(m+1)*DH + 16)*KPP, t);

        // ---- bias add ----
        float e[8][8];
#pragma unroll
        for (int u = 0; u < 8; u++) {
            int qi = qb + u;
            float4 ex4 = *(const float4*)&exs[qi*32 + wkA];
            float eyA  = eys[qi*32 + hkA];
            float eyB  = eys[qi*32 + hkA + 16];
            float a0,a1,a2,a3;
            UPK2(a0,a1,acc2[u][0]); UPK2(a2,a3,acc2[u][1]);
            e[u][0] = a0 + ex4.x + eyA;
            e[u][1] = a1 + ex4.y + eyA;
            e[u][2] = a2 + ex4.z + eyA;
            e[u][3] = a3 + ex4.w + eyA;
            UPK2(a0,a1,acc2[u][2]); UPK2(a2,a3,acc2[u][3]);
            e[u][4] = a0 + ex4.x + eyB;
            e[u][5] = a1 + ex4.y + eyB;
            e[u][6] = a2 + ex4.z + eyB;
            e[u][7] = a3 + ex4.w + eyB;
        }

        // ---- softmax (4 warps per query group) ----
        float mx[8];
#pragma unroll
        for (int u = 0; u < 8; u++) {
            float v = e[u][0];
#pragma unroll
            for (int j = 1; j < 8; j++) v = fmaxf(v, e[u][j]);
#pragma unroll
            for (int s2 = 16; s2; s2 >>= 1) v = fmaxf(v, __shfl_xor_sync(0xffffffffu, v, s2));
            mx[u] = v;
        }
        if (lane == 0) {
#pragma unroll
            for (int u = 0; u < 8; u++) red[grp*32 + wgrp*8 + u] = mx[u];
        }
        __syncthreads();   // (5)
#pragma unroll
        for (int u = 0; u < 8; u++) {
            float v = red[grp*32 + u];
            v = fmaxf(v, red[grp*32 + 8  + u]);
            v = fmaxf(v, red[grp*32 + 16 + u]);
            v = fmaxf(v, red[grp*32 + 24 + u]);
            mx[u] = v;
        }
        float sme[8];
#pragma unroll
        for (int u = 0; u < 8; u++) {
            float s = 0.f;
#pragma unroll
            for (int j = 0; j < 8; j++) {
                float p = __expf(e[u][j] - mx[u]);
                e[u][j] = p;
                s += p;
            }
#pragma unroll
            for (int s2 = 16; s2; s2 >>= 1) s += __shfl_xor_sync(0xffffffffu, s, s2);
            sme[u] = s;
        }
        if (lane == 0) {
#pragma unroll
            for (int u = 0; u < 8; u++) red[64 + grp*32 + wgrp*8 + u] = sme[u];
        }
        __syncthreads();   // (6)
#pragma unroll
        for (int u = 0; u < 8; u++) {
            float s = red[64 + grp*32 + u] + red[64 + grp*32 + 8 + u]
                    + red[64 + grp*32 + 16 + u] + red[64 + grp*32 + 24 + u];
            float sc = mw / s;
#pragma unroll
            for (int j = 0; j < 8; j++) ab[u][j] += e[u][j] * sc;
        }
    }

    // ---- write combined attention ----
#pragma unroll
    for (int u = 0; u < 8; u++) {
        float* arow = g_Atn + ((size_t)n*HP + q0 + qb + u)*KPP;
        *(float4*)&arow[kqA]       = make_float4(ab[u][0], ab[u][1], ab[u][2], ab[u][3]);
        *(float4*)&arow[512 + kqA] = make_float4(ab[u][4], ab[u][5], ab[u][6], ab[u][7]);
    }
}

// =================================================================================
// Kernel 5: PV GEMM.  BM=64, BN=96, BK=16, 128 threads, 8x6 per thread.
// =================================================================================
__global__ __launch_bounds__(128) void pv_kernel()
{
    int n    = blockIdx.z;
    int row0 = blockIdx.x * 64;
    int o0   = blockIdx.y * 96;

    __shared__ float As[16][68];
    __shared__ float Bs[16][96];

    int t  = threadIdx.x;
    int tx = t & 15, ty = t >> 4;   // tx 0..15, ty 0..7

    const float* A = g_Atn + ((size_t)n*HP + row0)*KPP;
    const float* V = g_V + (size_t)n*KPP*CH + o0;

    ull acc2[8][3] = {};

    for (int k0 = 0; k0 < KPP; k0 += 16) {
#pragma unroll
        for (int i = 0; i < 8; i++) {
            int e = t + i*128;
            int row = e >> 4, k = e & 15;
            As[k][row] = A[(size_t)row*KPP + k0 + k];
        }
#pragma unroll
        for (int i = 0; i < 12; i++) {
            int e = t + i*128;
            int k = e / 96, col = e % 96;
            Bs[k][col] = V[(size_t)(k0 + k)*CH + col];
        }
        __syncthreads();
#pragma unroll
        for (int k = 0; k < 16; k++) {
            float4 a0 = *(const float4*)&As[k][ty*8];
            float4 a1 = *(const float4*)&As[k][ty*8 + 4];
            ull b0 = *(const ull*)&Bs[k][tx*6];
            ull b1 = *(const ull*)&Bs[k][tx*6 + 2];
            ull b2 = *(const ull*)&Bs[k][tx*6 + 4];
            ull pa;
            PK2(pa, a0.x, a0.x); FMA2(acc2[0][0], pa, b0); FMA2(acc2[0][1], pa, b1); FMA2(acc2[0][2], pa, b2);
            PK2(pa, a0.y, a0.y); FMA2(acc2[1][0], pa, b0); FMA2(acc2[1][1], pa, b1); FMA2(acc2[1][2], pa, b2);
            PK2(pa, a0.z, a0.z); FMA2(acc2[2][0], pa, b0); FMA2(acc2[2][1], pa, b1); FMA2(acc2[2][2], pa, b2);
            PK2(pa, a0.w, a0.w); FMA2(acc2[3][0], pa, b0); FMA2(acc2[3][1], pa, b1); FMA2(acc2[3][2], pa, b2);
            PK2(pa, a1.x, a1.x); FMA2(acc2[4][0], pa, b0); FMA2(acc2[4][1], pa, b1); FMA2(acc2[4][2], pa, b2);
            PK2(pa, a1.y, a1.y); FMA2(acc2[5][0], pa, b0); FMA2(acc2[5][1], pa, b1); FMA2(acc2[5][2], pa, b2);
            PK2(pa, a1.z, a1.z); FMA2(acc2[6][0], pa, b0); FMA2(acc2[6][1], pa, b1); FMA2(acc2[6][2], pa, b2);
            PK2(pa, a1.w, a1.w); FMA2(acc2[7][0], pa, b0); FMA2(acc2[7][1], pa, b1); FMA2(acc2[7][2], pa, b2);
        }
        __syncthreads();
    }

    float* O = g_O + ((size_t)n*HP + row0)*CH + o0;
#pragma unroll
    for (int i = 0; i < 8; i++) {
        float v0,v1,v2,v3,v4,v5;
        UPK2(v0,v1,acc2[i][0]);
        UPK2(v2,v3,acc2[i][1]);
        UPK2(v4,v5,acc2[i][2]);
        float* orow = O + (size_t)(ty*8 + i)*CH + tx*6;
        *(float2*)&orow[0] = make_float2(v0,v1);
        *(float2*)&orow[2] = make_float2(v2,v3);
        *(float2*)&orow[4] = make_float2(v4,v5);
    }
}

// =================================================================================
// Kernel 6: final projection + residual (FFMA2).  [unchanged]
// =================================================================================
__global__ __launch_bounds__(256) void proj_kernel(
    const float* __restrict__ x,
    const float* __restrict__ Wp,
    const float* __restrict__ bp,
    const float* __restrict__ gamma,
    float* __restrict__ out)
{
    int n  = blockIdx.z;
    int p0 = blockIdx.x * 64;
    int o0 = blockIdx.y * 64;
    const float* A = g_O + (size_t)n*HP*CH;

    __shared__ float As[32][68];
    __shared__ float Bs[32][68];

    int t  = threadIdx.x;
    int tx = t & 15, ty = t >> 4;
    ull acc2[4][2] = {};

    for (int c0 = 0; c0 < CH; c0 += 32) {
#pragma unroll
        for (int i = 0; i < 8; i++) {
            int idx = t + i*256;
            int pix = idx >> 5, c = idx & 31;
            As[c][pix] = A[(size_t)(p0 + pix)*CH + c0 + c];
        }
#pragma unroll
        for (int i = 0; i < 8; i++) {
            int idx = t + i*256;
            int o = idx >> 5, c = idx & 31;
            int oo = o0 + o;
            Bs[c][o] = (oo < CH) ? Wp[(size_t)oo*CH + c0 + c] : 0.f;
        }
        __syncthreads();
#pragma unroll
        for (int c = 0; c < 32; c++) {
            ulonglong2 a2 = *(const ulonglong2*)&As[c][tx*4];
            float4 b = *(const float4*)&Bs[c][ty*4];
            ull pb;
            PK2(pb, b.x, b.x); FMA2(acc2[0][0], pb, a2.x); FMA2(acc2[0][1], pb, a2.y);
            PK2(pb, b.y, b.y); FMA2(acc2[1][0], pb, a2.x); FMA2(acc2[1][1], pb, a2.y);
            PK2(pb, b.z, b.z); FMA2(acc2[2][0], pb, a2.x); FMA2(acc2[2][1], pb, a2.y);
            PK2(pb, b.w, b.w); FMA2(acc2[3][0], pb, a2.x); FMA2(acc2[3][1], pb, a2.y);
        }
        __syncthreads();
    }
    float g = gamma[0];
#pragma unroll
    for (int j = 0; j < 4; j++) {
        int o = o0 + ty*4 + j;
        if (o < CH) {
            float a0,a1,a2,a3;
            UPK2(a0,a1,acc2[j][0]);
            UPK2(a2,a3,acc2[j][1]);
            float bb = bp[o];
            size_t base = (size_t)n*CH*HP + (size_t)o*HP + p0 + tx*4;
            float4 xr = *(const float4*)(x + base);
            float4 v;
            v.x = g*(a0 + bb) + xr.x;
            v.y = g*(a1 + bb) + xr.y;
            v.z = g*(a2 + bb) + xr.z;
            v.w = g*(a3 + bb) + xr.w;
            *(float4*)(out + base) = v;
        }
    }
}

// =================================================================================
extern "C" void kernel_launch(void* const* d_in, const int* in_sizes, int n_in,
                              void* d_out, int out_size)
{
    const float* x     = (const float*)d_in[0];
    const float* Wq    = (const float*)d_in[1];
    const float* Wk    = (const float*)d_in[2];
    const float* Wv    = (const float*)d_in[3];
    const float* Wx    = (const float*)d_in[4];
    const float* Wy    = (const float*)d_in[5];
    const float* Wproj = (const float*)d_in[6];
    const float* bproj = (const float*)d_in[7];
    const float* Wc    = (const float*)d_in[8];
    const float* bc    = (const float*)d_in[9];
    const float* gamma = (const float*)d_in[10];
    float* out = (float*)d_out;

    cudaFuncSetAttribute(attn_e_kernel, cudaFuncAttributeMaxDynamicSharedMemorySize,
                         AE_TOT * (int)sizeof(float));

    qkv_kernel<<<dim3(64, 5, 6), 256>>>(x, Wq, Wk, Wv);        // 1
    pf_kernel<<<dim3(2048, 2), 144>>>(Wx, Wy);                 // 2
    ctx1_kernel<<<dim3(32, 2), 288>>>();                       // 3
    attn_e_kernel<<<dim3(HP/TQ, NB), 256,                      // 4  <- ncu window
                    AE_TOT * (int)sizeof(float)>>>(Wc, bc);
    pv_kernel<<<dim3(HP/64, 3, NB), 128>>>();                  // 5
    proj_kernel<<<dim3(64, 5, 2), 256>>>(x, Wproj, bproj, gamma, out);  // 6
}

// round 9
// speedup vs baseline: 2.2479x; 1.4698x over previous
#include <cuda_runtime.h>
#include <math.h>

#define NB  2
#define CH  288
#define HP  4096
#define KPP 1024
#define NH  9
#define DH  32
#define TQ  16

typedef unsigned long long ull;

// ---- packed f32x2 FMA (sm_103a FFMA2; PTX-only path) ----
#define FMA2(d, a, b) asm("fma.rn.f32x2 %0, %1, %2, %0;" : "+l"(d) : "l"(a), "l"(b))
#define PK2(d, lo, hi) asm("mov.b64 %0, {%1, %2};" : "=l"(d) : "r"(__float_as_uint(lo)), "r"(__float_as_uint(hi)))
#define UPK2(lo, hi, v) do { unsigned int _ul, _uh; \
    asm("mov.b64 {%0, %1}, %2;" : "=r"(_ul), "=r"(_uh) : "l"(v)); \
    (lo) = __uint_as_float(_ul); (hi) = __uint_as_float(_uh); } while (0)

// ---- cp.async helpers ----
#define CP_ASYNC16(dst_u32, src_ptr) \
    asm volatile("cp.async.cg.shared.global [%0], [%1], 16;" :: "r"(dst_u32), "l"(src_ptr))
#define CP_COMMIT() asm volatile("cp.async.commit_group;")
#define CP_WAIT(n)  asm volatile("cp.async.wait_group %0;" :: "n"(n))

// ---------------- device scratch ----------------
__device__ float g_Q   [NB*HP*CH];
__device__ float g_KTd [NB*NH*DH*KPP];   // k[n][m][dd][kp]
__device__ float g_V   [NB*KPP*CH];
__device__ float g_O   [NB*HP*CH];
__device__ float g_PFX [NH*64*32*DH];    // pfx[m][a][d][kk]  (TRANSPOSED: kk fastest)
__device__ float g_PFY [NH*64*32*DH];    // pfy[m][a][d][kk]
__device__ float g_Atn [NB*HP*KPP];      // combined attention weights
__device__ float g_ctxp[NB*32*CH];

// =================================================================================
// Kernel 1: Q/K/V projections (FFMA2 inner).  [unchanged]
// =================================================================================
__global__ __launch_bounds__(256) void qkv_kernel(
    const float* __restrict__ x,
    const float* __restrict__ Wq,
    const float* __restrict__ Wk,
    const float* __restrict__ Wv)
{
    int which = blockIdx.z >> 1;
    int n     = blockIdx.z & 1;
    int rows  = (which == 0) ? HP : KPP;
    int p0    = blockIdx.x * 64;
    if (p0 >= rows) return;
    int o0    = blockIdx.y * 64;

    const float* W = (which == 0) ? Wq : (which == 1 ? Wk : Wv);
    const float* xb = x + (size_t)n*CH*HP;

    __shared__ float As[32][64];
    __shared__ float Bs[32][68];

    int t  = threadIdx.x;
    int tx = t & 15, ty = t >> 4;
    ull acc2[4][2] = {};

    for (int c0 = 0; c0 < CH; c0 += 32) {
#pragma unroll
        for (int i = 0; i < 8; i++) {
            int idx = t + i*256;
            int c = idx >> 6, pix = idx & 63;
            int row = p0 + pix;
            int pixel = (which == 0) ? row : (((row >> 5) << 7) | ((row & 31) << 1));
            As[c][pix] = xb[(size_t)(c0 + c)*HP + pixel];
        }
#pragma unroll
        for (int i = 0; i < 8; i++) {
            int idx = t + i*256;
            int o = idx >> 5, c = idx & 31;
            int oo = o0 + o;
            Bs[c][o] = (oo < CH) ? W[(size_t)oo*CH + c0 + c] : 0.f;
        }
        __syncthreads();
#pragma unroll
        for (int c = 0; c < 32; c++) {
            float4 a = *(const float4*)&As[c][ty*4];
            ulonglong2 b2 = *(const ulonglong2*)&Bs[c][tx*4];
            ull pa;
            PK2(pa, a.x, a.x); FMA2(acc2[0][0], pa, b2.x); FMA2(acc2[0][1], pa, b2.y);
            PK2(pa, a.y, a.y); FMA2(acc2[1][0], pa, b2.x); FMA2(acc2[1][1], pa, b2.y);
            PK2(pa, a.z, a.z); FMA2(acc2[2][0], pa, b2.x); FMA2(acc2[2][1], pa, b2.y);
            PK2(pa, a.w, a.w); FMA2(acc2[3][0], pa, b2.x); FMA2(acc2[3][1], pa, b2.y);
        }
        __syncthreads();
    }
    float acc[4][4];
#pragma unroll
    for (int i = 0; i < 4; i++) {
        UPK2(acc[i][0], acc[i][1], acc2[i][0]);
        UPK2(acc[i][2], acc[i][3], acc2[i][1]);
    }
    int o = o0 + tx*4;
    if (o >= CH) return;

    if (which == 1) {
#pragma unroll
        for (int i = 0; i < 4; i++) {
            int row = p0 + ty*4 + i;
#pragma unroll
            for (int c = 0; c < 4; c++) {
                int oo = o + c;
                g_KTd[(((size_t)n*NH + (oo >> 5))*DH + (oo & 31))*KPP + row] = acc[i][c];
            }
        }
    } else {
        float* out = (which == 0) ? (g_Q + (size_t)n*HP*CH) : (g_V + (size_t)n*KPP*CH);
#pragma unroll
        for (int i = 0; i < 4; i++) {
            int row = p0 + ty*4 + i;
            *(float4*)&out[(size_t)row*CH + o] =
                make_float4(acc[i][0], acc[i][1], acc[i][2], acc[i][3]);
        }
    }
}

// =================================================================================
// Kernel 2: positional factor tables.  CHANGED: write layout [m][a][d][kk]
// (kk fastest) so attention bias loads are lane-coalesced.
// =================================================================================
__global__ void pf_kernel(const float* __restrict__ Wx, const float* __restrict__ Wy)
{
    int a = blockIdx.x >> 5;
    int b = blockIdx.x & 31;
    const float* W = blockIdx.y ? Wy : Wx;
    float* out = blockIdx.y ? g_PFY : g_PFX;

    __shared__ float emb[144];
    int t = threadIdx.x;
    float diff = (float)a - 2.0f*(float)b;
    if (t < 72) {
        float dm  = powf(1000.0f, (4.0f/288.0f)*(float)t);
        float arg = diff / dm;
        emb[t]      = sinf(arg);
        emb[72 + t] = cosf(arg);
    }
    __syncthreads();
    const float inv_sqrt2 = 0.7071067811865476f;
    for (int j = t; j < CH; j += 144) {
        float s = 0.f;
        const float* wr = W + (size_t)j*144;
#pragma unroll 8
        for (int f = 0; f < 144; f++) s += emb[f]*wr[f];
        int m = j >> 5, dd = j & 31;
        out[(((size_t)m*64 + a)*32 + dd)*32 + b] = s * inv_sqrt2;   // [m][a][dd][b]
    }
}

// =================================================================================
// Kernel 3: context partial sums.  [unchanged]
// =================================================================================
__global__ __launch_bounds__(288) void ctx1_kernel()
{
    int n = blockIdx.y, b = blockIdx.x, t = threadIdx.x;
    const float* q = g_Q + ((size_t)n*HP + b*128)*CH + t;
    float s = 0.f;
#pragma unroll 8
    for (int p = 0; p < 128; p++) s += q[(size_t)p*CH];
    g_ctxp[((size_t)n*32 + b)*CH + t] = s;
}

// =================================================================================
// Kernel 4: attention.  CHANGED: bias dots read the transposed PF layout with
// kk = lane (coalesced 128B loads).  Everything else identical to R8.
// =================================================================================
#define AE_QS  0
#define AE_K0  4608
#define AE_K1  (AE_K0 + 16*1024)
#define AE_EX  (AE_K1 + 16*1024)
#define AE_EY  (AE_EX + 512)
#define AE_RD  (AE_EY + 512)
#define AE_CS  (AE_RD + 128)
#define AE_MX  (AE_CS + 288)
#define AE_TOT (AE_MX + 16)          // 38832 floats = 155,328 B

__device__ __forceinline__ void stage_half(float* buf, const float* kb, int t)
{
    unsigned int dst = (unsigned int)__cvta_generic_to_shared(buf);
#pragma unroll
    for (int i = 0; i < 16; i++) {
        int idx = t + i*256;
        int row = idx >> 8, c4 = (idx & 255)*4;
        CP_ASYNC16(dst + (unsigned int)(row*1024 + c4)*4u, kb + (size_t)row*KPP + c4);
    }
    CP_COMMIT();
}

__global__ __launch_bounds__(256, 1) void attn_e_kernel(
    const float* __restrict__ Wc, const float* __restrict__ bc)
{
    extern __shared__ float sm[];
    float* Qs   = sm + AE_QS;
    float* K0   = sm + AE_K0;
    float* K1   = sm + AE_K1;
    float* exs  = sm + AE_EX;
    float* eys  = sm + AE_EY;
    float* red  = sm + AE_RD;
    float* cs   = sm + AE_CS;
    float* mixs = sm + AE_MX;

    int n  = blockIdx.y;
    int q0 = blockIdx.x * TQ;
    int h  = q0 >> 6;
    int wbase = q0 & 63;
    int t  = threadIdx.x;
    int warp = t >> 5, lane = t & 31;

    const float* khead = g_KTd + ((size_t)n*NH)*DH*KPP;

    // ---- prefetch head 0 (both halves) ----
    stage_half(K0, khead, t);
    stage_half(K1, khead + 16*KPP, t);

    // ---- mixw: finish context reduction in-block (strided: CH > blockDim) ----
    for (int c = t; c < CH; c += 256) {
        float s = 0.f;
#pragma unroll
        for (int b = 0; b < 32; b++) s += g_ctxp[((size_t)n*32 + b)*CH + c];
        cs[c] = s * (1.0f/HP);
    }

    // ---- load Q tile (16 x 288 = 1152 float4) ----
    {
        const float4* src = (const float4*)(g_Q + ((size_t)n*HP + q0)*CH);
        float4* dst = (float4*)Qs;
#pragma unroll
        for (int i = 0; i < 5; i++) {
            int idx = t + i*256;
            if (idx < 1152) dst[idx] = src[idx];
        }
    }
    __syncthreads();
    if (t < NH) {
        float l = bc[t];
        const float* wr = Wc + (size_t)t*CH;
#pragma unroll 8
        for (int o = 0; o < CH; o++) l += cs[o]*wr[o];
        mixs[t] = l;
    }
    __syncthreads();
    if (t == 0) {
        float mx = mixs[0];
        for (int j = 1; j < NH; j++) mx = fmaxf(mx, mixs[j]);
        float sum = 0.f;
        for (int j = 0; j < NH; j++) { float e2 = expf(mixs[j]-mx); mixs[j] = e2; sum += e2; }
        float inv = 1.0f/sum;
        for (int j = 0; j < NH; j++) mixs[j] *= inv;
    }

    const int kt   = t & 127;
    const int kqA  = kt * 4;
    const int grp  = t >> 7;
    const int qb   = grp * 8;
    const int wgrp = warp & 3;

    const int wkA = kqA & 31;
    const int hkA = kqA >> 5;

    float ab[8][8] = {};

    for (int m = 0; m < NH; m++) {
        // ---- wait half A of head m; barrier also covers mixs/Q/exs reuse ----
        CP_WAIT(1);
        __syncthreads();   // (1)

        float mw = mixs[m];

        // ---- bias dots (2 per thread; kk = lane -> coalesced PF loads) ----
#pragma unroll
        for (int r = 0; r < 2; r++) {
            int e  = t + r*256;
            int qi = e >> 5, kk = e & 31;   // kk == lane within each warp
            const float* qp = Qs + qi*CH + m*DH;
            const float* px = g_PFX + (((size_t)m*64 + wbase + qi)*32)*32 + kk;
            const float* py = g_PFY + (((size_t)m*64 + h)*32)*32 + kk;
            float sx = 0.f, sy = 0.f;
#pragma unroll
            for (int d = 0; d < DH; d++) {
                float qv = qp[d];
                sx += qv * px[d*32];
                sy += qv * py[d*32];
            }
            exs[e] = sx; eys[e] = sy;
        }

        ull acc2[8][4] = {};

        // ---- QK half A (d = 0..15) ----
#pragma unroll
        for (int d4 = 0; d4 < 4; d4++) {
            const float* kbase = K0 + (d4*4)*1024;
            ulonglong2 kA0 = *(const ulonglong2*)(kbase          + kqA);
            ulonglong2 kA1 = *(const ulonglong2*)(kbase + 1024   + kqA);
            ulonglong2 kA2 = *(const ulonglong2*)(kbase + 2048   + kqA);
            ulonglong2 kA3 = *(const ulonglong2*)(kbase + 3072   + kqA);
            ulonglong2 kB0 = *(const ulonglong2*)(kbase + 512    + kqA);
            ulonglong2 kB1 = *(const ulonglong2*)(kbase + 1536   + kqA);
            ulonglong2 kB2 = *(const ulonglong2*)(kbase + 2560   + kqA);
            ulonglong2 kB3 = *(const ulonglong2*)(kbase + 3584   + kqA);
#pragma unroll
            for (int u = 0; u < 8; u++) {
                float4 qq = *(const float4*)&Qs[(qb+u)*CH + m*DH + d4*4];
                ull pa;
                PK2(pa, qq.x, qq.x);
                FMA2(acc2[u][0], pa, kA0.x); FMA2(acc2[u][1], pa, kA0.y);
                FMA2(acc2[u][2], pa, kB0.x); FMA2(acc2[u][3], pa, kB0.y);
                PK2(pa, qq.y, qq.y);
                FMA2(acc2[u][0], pa, kA1.x); FMA2(acc2[u][1], pa, kA1.y);
                FMA2(acc2[u][2], pa, kB1.x); FMA2(acc2[u][3], pa, kB1.y);
                PK2(pa, qq.z, qq.z);
                FMA2(acc2[u][0], pa, kA2.x); FMA2(acc2[u][1], pa, kA2.y);
                FMA2(acc2[u][2], pa, kB2.x); FMA2(acc2[u][3], pa, kB2.y);
                PK2(pa, qq.w, qq.w);
                FMA2(acc2[u][0], pa, kA3.x); FMA2(acc2[u][1], pa, kA3.y);
                FMA2(acc2[u][2], pa, kB3.x); FMA2(acc2[u][3], pa, kB3.y);
            }
        }
        __syncthreads();   // (2) done reading K0
        if (m < NH-1) stage_half(K0, khead + (size_t)(m+1)*DH*KPP, t);

        if (m < NH-1) { CP_WAIT(1); } else { CP_WAIT(0); }
        __syncthreads();   // (3) K1 ready

        // ---- QK half B (d = 16..31) ----
#pragma unroll
        for (int d4 = 0; d4 < 4; d4++) {
            const float* kbase = K1 + (d4*4)*1024;
            ulonglong2 kA0 = *(const ulonglong2*)(kbase          + kqA);
            ulonglong2 kA1 = *(const ulonglong2*)(kbase + 1024   + kqA);
            ulonglong2 kA2 = *(const ulonglong2*)(kbase + 2048   + kqA);
            ulonglong2 kA3 = *(const ulonglong2*)(kbase + 3072   + kqA);
            ulonglong2 kB0 = *(const ulonglong2*)(kbase + 512    + kqA);
            ulonglong2 kB1 = *(const ulonglong2*)(kbase + 1536   + kqA);
            ulonglong2 kB2 = *(const ulonglong2*)(kbase + 2560   + kqA);
            ulonglong2 kB3 = *(const ulonglong2*)(kbase + 3584   + kqA);
#pragma unroll
            for (int u = 0; u < 8; u++) {
                float4 qq = *(const float4*)&Qs[(qb+u)*CH + m*DH + 16 + d4*4];
                ull pa;
                PK2(pa, qq.x, qq.x);
                FMA2(acc2[u][0], pa, kA0.x); FMA2(acc2[u][1], pa, kA0.y);
                FMA2(acc2[u][2], pa, kB0.x); FMA2(acc2[u][3], pa, kB0.y);
                PK2(pa, qq.y, qq.y);
                FMA2(acc2[u][0], pa, kA1.x); FMA2(acc2[u][1], pa, kA1.y);
                FMA2(acc2[u][2], pa, kB1.x); FMA2(acc2[u][3], pa, kB1.y);
                PK2(pa, qq.z, qq.z);
                FMA2(acc2[u][0], pa, kA2.x); FMA2(acc2[u][1], pa, kA2.y);
                FMA2(acc2[u][2], pa, kB2.x); FMA2(acc2[u][3], pa, kB2.y);
                PK2(pa, qq.w, qq.w);
                FMA2(acc2[u][0], pa, kA3.x); FMA2(acc2[u][1], pa, kA3.y);
                FMA2(acc2[u][2], pa, kB3.x); FMA2(acc2[u][3], pa, kB3.y);
            }
        }
        __syncthreads();   // (4) done reading K1; exs/eys visible
        if (m < NH-1) stage_half(K1, khead + ((size_t)(m+1)*DH + 16)*KPP, t);

        // ---- bias add ----
        float e[8][8];
#pragma unroll
        for (int u = 0; u < 8; u++) {
            int qi = qb + u;
            float4 ex4 = *(const float4*)&exs[qi*32 + wkA];
            float eyA  = eys[qi*32 + hkA];
            float eyB  = eys[qi*32 + hkA + 16];
            float a0,a1,a2,a3;
            UPK2(a0,a1,acc2[u][0]); UPK2(a2,a3,acc2[u][1]);
            e[u][0] = a0 + ex4.x + eyA;
            e[u][1] = a1 + ex4.y + eyA;
            e[u][2] = a2 + ex4.z + eyA;
            e[u][3] = a3 + ex4.w + eyA;
            UPK2(a0,a1,acc2[u][2]); UPK2(a2,a3,acc2[u][3]);
            e[u][4] = a0 + ex4.x + eyB;
            e[u][5] = a1 + ex4.y + eyB;
            e[u][6] = a2 + ex4.z + eyB;
            e[u][7] = a3 + ex4.w + eyB;
        }

        // ---- softmax (4 warps per query group) ----
        float mx[8];
#pragma unroll
        for (int u = 0; u < 8; u++) {
            float v = e[u][0];
#pragma unroll
            for (int j = 1; j < 8; j++) v = fmaxf(v, e[u][j]);
#pragma unroll
            for (int s2 = 16; s2; s2 >>= 1) v = fmaxf(v, __shfl_xor_sync(0xffffffffu, v, s2));
            mx[u] = v;
        }
        if (lane == 0) {
#pragma unroll
            for (int u = 0; u < 8; u++) red[grp*32 + wgrp*8 + u] = mx[u];
        }
        __syncthreads();   // (5)
#pragma unroll
        for (int u = 0; u < 8; u++) {
            float v = red[grp*32 + u];
            v = fmaxf(v, red[grp*32 + 8  + u]);
            v = fmaxf(v, red[grp*32 + 16 + u]);
            v = fmaxf(v, red[grp*32 + 24 + u]);
            mx[u] = v;
        }
        float sme[8];
#pragma unroll
        for (int u = 0; u < 8; u++) {
            float s = 0.f;
#pragma unroll
            for (int j = 0; j < 8; j++) {
                float p = __expf(e[u][j] - mx[u]);
                e[u][j] = p;
                s += p;
            }
#pragma unroll
            for (int s2 = 16; s2; s2 >>= 1) s += __shfl_xor_sync(0xffffffffu, s, s2);
            sme[u] = s;
        }
        if (lane == 0) {
#pragma unroll
            for (int u = 0; u < 8; u++) red[64 + grp*32 + wgrp*8 + u] = sme[u];
        }
        __syncthreads();   // (6)
#pragma unroll
        for (int u = 0; u < 8; u++) {
            float s = red[64 + grp*32 + u] + red[64 + grp*32 + 8 + u]
                    + red[64 + grp*32 + 16 + u] + red[64 + grp*32 + 24 + u];
            float sc = mw / s;
#pragma unroll
            for (int j = 0; j < 8; j++) ab[u][j] += e[u][j] * sc;
        }
    }

    // ---- write combined attention ----
#pragma unroll
    for (int u = 0; u < 8; u++) {
        float* arow = g_Atn + ((size_t)n*HP + q0 + qb + u)*KPP;
        *(float4*)&arow[kqA]       = make_float4(ab[u][0], ab[u][1], ab[u][2], ab[u][3]);
        *(float4*)&arow[512 + kqA] = make_float4(ab[u][4], ab[u][5], ab[u][6], ab[u][7]);
    }
}

// =================================================================================
// Kernel 5: PV GEMM.  [unchanged]
// =================================================================================
__global__ __launch_bounds__(128) void pv_kernel()
{
    int n    = blockIdx.z;
    int row0 = blockIdx.x * 64;
    int o0   = blockIdx.y * 96;

    __shared__ float As[16][68];
    __shared__ float Bs[16][96];

    int t  = threadIdx.x;
    int tx = t & 15, ty = t >> 4;

    const float* A = g_Atn + ((size_t)n*HP + row0)*KPP;
    const float* V = g_V + (size_t)n*KPP*CH + o0;

    ull acc2[8][3] = {};

    for (int k0 = 0; k0 < KPP; k0 += 16) {
#pragma unroll
        for (int i = 0; i < 8; i++) {
            int e = t + i*128;
            int row = e >> 4, k = e & 15;
            As[k][row] = A[(size_t)row*KPP + k0 + k];
        }
#pragma unroll
        for (int i = 0; i < 12; i++) {
            int e = t + i*128;
            int k = e / 96, col = e % 96;
            Bs[k][col] = V[(size_t)(k0 + k)*CH + col];
        }
        __syncthreads();
#pragma unroll
        for (int k = 0; k < 16; k++) {
            float4 a0 = *(const float4*)&As[k][ty*8];
            float4 a1 = *(const float4*)&As[k][ty*8 + 4];
            ull b0 = *(const ull*)&Bs[k][tx*6];
            ull b1 = *(const ull*)&Bs[k][tx*6 + 2];
            ull b2 = *(const ull*)&Bs[k][tx*6 + 4];
            ull pa;
            PK2(pa, a0.x, a0.x); FMA2(acc2[0][0], pa, b0); FMA2(acc2[0][1], pa, b1); FMA2(acc2[0][2], pa, b2);
            PK2(pa, a0.y, a0.y); FMA2(acc2[1][0], pa, b0); FMA2(acc2[1][1], pa, b1); FMA2(acc2[1][2], pa, b2);
            PK2(pa, a0.z, a0.z); FMA2(acc2[2][0], pa, b0); FMA2(acc2[2][1], pa, b1); FMA2(acc2[2][2], pa, b2);
            PK2(pa, a0.w, a0.w); FMA2(acc2[3][0], pa, b0); FMA2(acc2[3][1], pa, b1); FMA2(acc2[3][2], pa, b2);
            PK2(pa, a1.x, a1.x); FMA2(acc2[4][0], pa, b0); FMA2(acc2[4][1], pa, b1); FMA2(acc2[4][2], pa, b2);
            PK2(pa, a1.y, a1.y); FMA2(acc2[5][0], pa, b0); FMA2(acc2[5][1], pa, b1); FMA2(acc2[5][2], pa, b2);
            PK2(pa, a1.z, a1.z); FMA2(acc2[6][0], pa, b0); FMA2(acc2[6][1], pa, b1); FMA2(acc2[6][2], pa, b2);
            PK2(pa, a1.w, a1.w); FMA2(acc2[7][0], pa, b0); FMA2(acc2[7][1], pa, b1); FMA2(acc2[7][2], pa, b2);
        }
        __syncthreads();
    }

    float* O = g_O + ((size_t)n*HP + row0)*CH + o0;
#pragma unroll
    for (int i = 0; i < 8; i++) {
        float v0,v1,v2,v3,v4,v5;
        UPK2(v0,v1,acc2[i][0]);
        UPK2(v2,v3,acc2[i][1]);
        UPK2(v4,v5,acc2[i][2]);
        float* orow = O + (size_t)(ty*8 + i)*CH + tx*6;
        *(float2*)&orow[0] = make_float2(v0,v1);
        *(float2*)&orow[2] = make_float2(v2,v3);
        *(float2*)&orow[4] = make_float2(v4,v5);
    }
}

// =================================================================================
// Kernel 6: final projection + residual (FFMA2).  [unchanged]
// =================================================================================
__global__ __launch_bounds__(256) void proj_kernel(
    const float* __restrict__ x,
    const float* __restrict__ Wp,
    const float* __restrict__ bp,
    const float* __restrict__ gamma,
    float* __restrict__ out)
{
    int n  = blockIdx.z;
    int p0 = blockIdx.x * 64;
    int o0 = blockIdx.y * 64;
    const float* A = g_O + (size_t)n*HP*CH;

    __shared__ float As[32][68];
    __shared__ float Bs[32][68];

    int t  = threadIdx.x;
    int tx = t & 15, ty = t >> 4;
    ull acc2[4][2] = {};

    for (int c0 = 0; c0 < CH; c0 += 32) {
#pragma unroll
        for (int i = 0; i < 8; i++) {
            int idx = t + i*256;
            int pix = idx >> 5, c = idx & 31;
            As[c][pix] = A[(size_t)(p0 + pix)*CH + c0 + c];
        }
#pragma unroll
        for (int i = 0; i < 8; i++) {
            int idx = t + i*256;
            int o = idx >> 5, c = idx & 31;
            int oo = o0 + o;
            Bs[c][o] = (oo < CH) ? Wp[(size_t)oo*CH + c0 + c] : 0.f;
        }
        __syncthreads();
#pragma unroll
        for (int c = 0; c < 32; c++) {
            ulonglong2 a2 = *(const ulonglong2*)&As[c][tx*4];
            float4 b = *(const float4*)&Bs[c][ty*4];
            ull pb;
            PK2(pb, b.x, b.x); FMA2(acc2[0][0], pb, a2.x); FMA2(acc2[0][1], pb, a2.y);
            PK2(pb, b.y, b.y); FMA2(acc2[1][0], pb, a2.x); FMA2(acc2[1][1], pb, a2.y);
            PK2(pb, b.z, b.z); FMA2(acc2[2][0], pb, a2.x); FMA2(acc2[2][1], pb, a2.y);
            PK2(pb, b.w, b.w); FMA2(acc2[3][0], pb, a2.x); FMA2(acc2[3][1], pb, a2.y);
        }
        __syncthreads();
    }
    float g = gamma[0];
#pragma unroll
    for (int j = 0; j < 4; j++) {
        int o = o0 + ty*4 + j;
        if (o < CH) {
            float a0,a1,a2,a3;
            UPK2(a0,a1,acc2[j][0]);
            UPK2(a2,a3,acc2[j][1]);
            float bb = bp[o];
            size_t base = (size_t)n*CH*HP + (size_t)o*HP + p0 + tx*4;
            float4 xr = *(const float4*)(x + base);
            float4 v;
            v.x = g*(a0 + bb) + xr.x;
            v.y = g*(a1 + bb) + xr.y;
            v.z = g*(a2 + bb) + xr.z;
            v.w = g*(a3 + bb) + xr.w;
            *(float4*)(out + base) = v;
        }
    }
}

// =================================================================================
extern "C" void kernel_launch(void* const* d_in, const int* in_sizes, int n_in,
                              void* d_out, int out_size)
{
    const float* x     = (const float*)d_in[0];
    const float* Wq    = (const float*)d_in[1];
    const float* Wk    = (const float*)d_in[2];
    const float* Wv    = (const float*)d_in[3];
    const float* Wx    = (const float*)d_in[4];
    const float* Wy    = (const float*)d_in[5];
    const float* Wproj = (const float*)d_in[6];
    const float* bproj = (const float*)d_in[7];
    const float* Wc    = (const float*)d_in[8];
    const float* bc    = (const float*)d_in[9];
    const float* gamma = (const float*)d_in[10];
    float* out = (float*)d_out;

    cudaFuncSetAttribute(attn_e_kernel, cudaFuncAttributeMaxDynamicSharedMemorySize,
                         AE_TOT * (int)sizeof(float));

    qkv_kernel<<<dim3(64, 5, 6), 256>>>(x, Wq, Wk, Wv);        // 1
    pf_kernel<<<dim3(2048, 2), 144>>>(Wx, Wy);                 // 2
    ctx1_kernel<<<dim3(32, 2), 288>>>();                       // 3
    attn_e_kernel<<<dim3(HP/TQ, NB), 256,                      // 4  <- ncu window
                    AE_TOT * (int)sizeof(float)>>>(Wc, bc);
    pv_kernel<<<dim3(HP/64, 3, NB), 128>>>();                  // 5
    proj_kernel<<<dim3(64, 5, 2), 256>>>(x, Wproj, bproj, gamma, out);  // 6
}